// round 4
// baseline (speedup 1.0000x reference)
#include <cuda_runtime.h>
#include <math.h>

// Problem dims
#define NB 2
#define NC 16
#define NAM 4
#define NHEADS 8
#define NF 1024
#define NW 1024
#define NHD 128

#define BKDIM 16
#define STR_K 136  // k-major smem stride (words): conflict-free frags (8*tig+gid)
#define STR_M 20   // m-major smem stride (words): conflict-free frags (20*gid+tig)
#define SLAB_K (BKDIM * STR_K)   // 2176
#define SLAB_M (128 * STR_M)     // 2560

// ---------------- scratch (device globals; no runtime allocation) ----------------
__device__ float g_y[3][8][NF * NW];     // conv outputs for q,k,v   [tensor][b*4+am][h*1024+w]
__device__ float g_t[3][8][NW * NF];     // qT,kT,vT                 [tensor][b*4+am][w*1024+f]
__device__ float g_a[8][NW * NF];        // attention out            [b*4+am][w*1024+f]
__device__ float g_ao[8][NW * NF];       // after dw channel mix     [b*4+am][w*1024+h]
__device__ float g_a2[8][NF * NW];       // after wo_pw              [b*4+am][f*1024+w]
__device__ float g_psum[64 * 1024 * 16]; // per-row exp partial sums [bh*1024+row][16]
__device__ float g_cos[NW * (NHD / 2)];
__device__ float g_sin[NW * (NHD / 2)];

// ---------------- async-copy helpers ----------------
__device__ __forceinline__ unsigned sptr(const void* p) {
    return (unsigned)__cvta_generic_to_shared(p);
}
__device__ __forceinline__ void cpasync16(const void* dst_smem, const void* src_gmem) {
    asm volatile("cp.async.cg.shared.global [%0], [%1], 16;" ::"r"(sptr(dst_smem)),
                 "l"(src_gmem));
}
#define CP_COMMIT asm volatile("cp.async.commit_group;")
#define CP_WAIT1 asm volatile("cp.async.wait_group 1;")

// ---------------- mma ----------------
__device__ __forceinline__ void mma_tf32(float* c, unsigned a0, unsigned a1, unsigned a2,
                                         unsigned a3, unsigned b0, unsigned b1) {
    asm volatile(
        "mma.sync.aligned.m16n8k8.row.col.f32.tf32.tf32.f32 "
        "{%0,%1,%2,%3}, {%4,%5,%6,%7}, {%8,%9}, {%0,%1,%2,%3};"
        : "+f"(c[0]), "+f"(c[1]), "+f"(c[2]), "+f"(c[3])
        : "r"(a0), "r"(a1), "r"(a2), "r"(a3), "r"(b0), "r"(b1));
}

// 128x128 C tile. 8 warps as 4(M)x2(N); warp tile 32x64 = 2 x 8 mma frags.
template <bool AKM, bool BKM>
__device__ __forceinline__ void frag_compute(const float* As, const float* Bs,
                                             float (&acc)[2][8][4], int gid, int tig,
                                             int warpM, int warpN) {
#pragma unroll
    for (int kk = 0; kk < 2; kk++) {
        const int k = kk * 8;
        unsigned af[2][4];
#pragma unroll
        for (int mt = 0; mt < 2; mt++) {
            int rb = warpM * 32 + mt * 16 + gid;
            af[mt][0] = __float_as_uint(AKM ? As[(k + tig) * STR_K + rb]
                                            : As[rb * STR_M + k + tig]);
            af[mt][1] = __float_as_uint(AKM ? As[(k + tig) * STR_K + rb + 8]
                                            : As[(rb + 8) * STR_M + k + tig]);
            af[mt][2] = __float_as_uint(AKM ? As[(k + 4 + tig) * STR_K + rb]
                                            : As[rb * STR_M + k + 4 + tig]);
            af[mt][3] = __float_as_uint(AKM ? As[(k + 4 + tig) * STR_K + rb + 8]
                                            : As[(rb + 8) * STR_M + k + 4 + tig]);
        }
        unsigned bf[8][2];
#pragma unroll
        for (int nt = 0; nt < 8; nt++) {
            int cb = warpN * 64 + nt * 8 + gid;
            bf[nt][0] = __float_as_uint(BKM ? Bs[(k + tig) * STR_K + cb]
                                            : Bs[cb * STR_M + k + tig]);
            bf[nt][1] = __float_as_uint(BKM ? Bs[(k + 4 + tig) * STR_K + cb]
                                            : Bs[cb * STR_M + k + 4 + tig]);
        }
#pragma unroll
        for (int mt = 0; mt < 2; mt++)
#pragma unroll
            for (int nt = 0; nt < 8; nt++)
                mma_tf32(acc[mt][nt], af[mt][0], af[mt][1], af[mt][2], af[mt][3], bf[nt][0],
                         bf[nt][1]);
    }
}

// copy one 16(k) x 128(mn) k-major slab
__device__ __forceinline__ void copy_kmaj(float* buf, const float* src, int tid) {
#pragma unroll
    for (int i = 0; i < 2; i++) {
        int idx = tid + i * 256;
        int row = idx >> 5, c = (idx & 31) * 4;
        cpasync16(&buf[row * STR_K + c], &src[(size_t)row * 1024 + c]);
    }
}
// copy one 128(mn) x 16(k) m-major slab
__device__ __forceinline__ void copy_mmaj(float* buf, const float* src, int tid) {
#pragma unroll
    for (int i = 0; i < 2; i++) {
        int idx = tid + i * 256;
        int row = idx >> 2, c = (idx & 3) * 4;
        cpasync16(&buf[row * STR_M + c], &src[(size_t)row * 1024 + c]);
    }
}

// ---------------- RoPE table init ----------------
__global__ void rope_init_kernel() {
    int idx = blockIdx.x * blockDim.x + threadIdx.x;
    if (idx >= NW * 64) return;
    int w = idx >> 6, j = idx & 63;
    double inv = exp(-((double)(2 * j) / (double)NHD) * log(10000.0));
    double ang = (double)w * inv;
    g_cos[idx] = (float)cos(ang);
    g_sin[idx] = (float)sin(ang);
}

// ---------------- conv 3x3 (16 -> 4) producing q,k,v conv outputs in one pass ----------------
__global__ __launch_bounds__(256) void conv_qkv_kernel(
    const float* __restrict__ x,
    const float* __restrict__ wq, const float* __restrict__ bq,
    const float* __restrict__ wk, const float* __restrict__ bk,
    const float* __restrict__ wv, const float* __restrict__ bv) {
    __shared__ float sx[4][18][68];
    __shared__ float sw[3 * 4 * 16 * 9];
    const int b = blockIdx.x;
    const int h0 = blockIdx.y * 16;
    const int w0 = blockIdx.z * 64;
    const int tx = threadIdx.x, ty = threadIdx.y;
    const int tid = ty * 16 + tx;

    for (int i = tid; i < 576; i += 256) {
        sw[i] = wq[i];
        sw[576 + i] = wk[i];
        sw[1152 + i] = wv[i];
    }

    float acc[12][4];
#pragma unroll
    for (int o = 0; o < 12; o++)
#pragma unroll
        for (int p = 0; p < 4; p++) acc[o][p] = 0.f;

    for (int cc = 0; cc < 16; cc += 4) {
        __syncthreads();
        for (int e = tid; e < 4 * 18 * 66; e += 256) {
            int ch = e / (18 * 66);
            int r = (e / 66) % 18;
            int cl = e % 66;
            int gh = h0 + r - 1, gw = w0 + cl - 1;
            float v = 0.f;
            if ((unsigned)gh < 1024u && (unsigned)gw < 1024u)
                v = x[(((size_t)(b * 16 + cc + ch)) << 20) + gh * 1024 + gw];
            sx[ch][r][cl] = v;
        }
        __syncthreads();
#pragma unroll
        for (int ch = 0; ch < 4; ch++) {
#pragma unroll
            for (int dy = 0; dy < 3; dy++) {
                float xr[6];
#pragma unroll
                for (int i = 0; i < 6; i++) xr[i] = sx[ch][ty + dy][tx * 4 + i];
#pragma unroll
                for (int dx = 0; dx < 3; dx++) {
                    int widx = (cc + ch) * 9 + dy * 3 + dx;
#pragma unroll
                    for (int o = 0; o < 12; o++) {
                        float wv_ = sw[(o >> 2) * 576 + (o & 3) * 144 + widx];
#pragma unroll
                        for (int p = 0; p < 4; p++) acc[o][p] += wv_ * xr[p + dx];
                    }
                }
            }
        }
    }

    int gh = h0 + ty, gw = w0 + tx * 4;
#pragma unroll
    for (int t = 0; t < 3; t++) {
        const float* bias = (t == 0) ? bq : (t == 1) ? bk : bv;
#pragma unroll
        for (int m = 0; m < 4; m++) {
            float bb = bias[m];
            float4 v = make_float4(acc[t * 4 + m][0] + bb, acc[t * 4 + m][1] + bb,
                                   acc[t * 4 + m][2] + bb, acc[t * 4 + m][3] + bb);
            *(float4*)&g_y[t][b * 4 + m][gh * 1024 + gw] = v;
        }
    }
}

// ---------------- pw linear: OutT[w,f] = sum_h Wt[f,h] * Y[h,w]; optional RoPE ----------------
// dyn smem: As 3 x SLAB_K (k-major), Bs 3 x SLAB_M (n-major)
__global__ __launch_bounds__(256, 2) void gemm_pw_t(const float* __restrict__ Wpw, int t,
                                                    int do_rope) {
    const int m0 = blockIdx.x * 128;  // w
    const int n0 = blockIdx.y * 128;  // f
    const int b4 = blockIdx.z;
    const int am = b4 & 3;
    const float* Y = g_y[t][b4];
    const float* Wt = Wpw + ((size_t)am << 20);
    float* Out = g_t[t][b4];

    extern __shared__ __align__(16) float sh[];
    float* ABUF[3] = {sh, sh + SLAB_K, sh + 2 * SLAB_K};
    float* BBUF[3] = {sh + 3 * SLAB_K, sh + 3 * SLAB_K + SLAB_M, sh + 3 * SLAB_K + 2 * SLAB_M};
    const int tid = threadIdx.x;
    const int lane = tid & 31, warp = tid >> 5, warpM = warp & 3, warpN = warp >> 2;
    const int gid = lane >> 2, tig = lane & 3;

    float acc[2][8][4] = {};

    copy_kmaj(ABUF[0], Y + m0, tid);
    copy_mmaj(BBUF[0], Wt + (size_t)n0 * 1024, tid);
    CP_COMMIT;
    copy_kmaj(ABUF[1], Y + (size_t)16 * 1024 + m0, tid);
    copy_mmaj(BBUF[1], Wt + (size_t)n0 * 1024 + 16, tid);
    CP_COMMIT;

    for (int it = 0; it < 64; it++) {
        CP_WAIT1;
        __syncthreads();
        if (it + 2 < 64) {
            int nx = (it + 2) % 3;
            copy_kmaj(ABUF[nx], Y + (size_t)(it + 2) * 16 * 1024 + m0, tid);
            copy_mmaj(BBUF[nx], Wt + (size_t)n0 * 1024 + (it + 2) * 16, tid);
        }
        CP_COMMIT;
        frag_compute<true, false>(ABUF[it % 3], BBUF[it % 3], acc, gid, tig, warpM, warpN);
    }

#pragma unroll
    for (int mt = 0; mt < 2; mt++)
#pragma unroll
        for (int half = 0; half < 2; half++) {
            int w = m0 + warpM * 32 + mt * 16 + gid + half * 8;
#pragma unroll
            for (int nt = 0; nt < 8; nt++) {
                int f = n0 + warpN * 64 + nt * 8 + 2 * tig;
                float v0 = acc[mt][nt][half * 2 + 0];
                float v1 = acc[mt][nt][half * 2 + 1];
                if (do_rope) {
                    int j0 = (f >> 1) & 63;
                    float c = g_cos[w * 64 + j0], s = g_sin[w * 64 + j0];
                    float e = v0 * c - v1 * s, o = v1 * c + v0 * s;
                    v0 = e;
                    v1 = o;
                }
                *(float2*)&Out[(size_t)w * 1024 + f] = make_float2(v0, v1);
            }
        }
}

// ---------------- S = q k^T / 32 + prev_qk + mask; fused per-row exp partial sums ----------
// dyn smem: As/Bs 3 x SLAB_M each
__global__ __launch_bounds__(256, 2) void gemm_qk_t(const float* __restrict__ prev_qk,
                                                    const float* __restrict__ mask,
                                                    float* __restrict__ qk_out) {
    const int m0 = blockIdx.x * 128;
    const int n0 = blockIdx.y * 128;
    const int bh = blockIdx.z;
    const int b4 = bh >> 3, head = bh & 7;
    const float* Qb = g_t[0][b4] + head * 128;
    const float* Kb = g_t[1][b4] + head * 128;

    extern __shared__ __align__(16) float sh[];
    float* ABUF[3] = {sh, sh + SLAB_M, sh + 2 * SLAB_M};
    float* BBUF[3] = {sh + 3 * SLAB_M, sh + 4 * SLAB_M, sh + 5 * SLAB_M};
    const int tid = threadIdx.x;
    const int lane = tid & 31, warp = tid >> 5, warpM = warp & 3, warpN = warp >> 2;
    const int gid = lane >> 2, tig = lane & 3;

    float acc[2][8][4] = {};

    copy_mmaj(ABUF[0], Qb + (size_t)m0 * 1024, tid);
    copy_mmaj(BBUF[0], Kb + (size_t)n0 * 1024, tid);
    CP_COMMIT;
    copy_mmaj(ABUF[1], Qb + (size_t)m0 * 1024 + 16, tid);
    copy_mmaj(BBUF[1], Kb + (size_t)n0 * 1024 + 16, tid);
    CP_COMMIT;

    for (int it = 0; it < 8; it++) {
        CP_WAIT1;
        __syncthreads();
        if (it + 2 < 8) {
            int nx = (it + 2) % 3;
            copy_mmaj(ABUF[nx], Qb + (size_t)m0 * 1024 + (it + 2) * 16, tid);
            copy_mmaj(BBUF[nx], Kb + (size_t)n0 * 1024 + (it + 2) * 16, tid);
        }
        CP_COMMIT;
        frag_compute<false, false>(ABUF[it % 3], BBUF[it % 3], acc, gid, tig, warpM, warpN);
    }

    const float* prevb = prev_qk + ((size_t)bh << 20);
    float* outb = qk_out + ((size_t)bh << 20);
#pragma unroll
    for (int mt = 0; mt < 2; mt++)
#pragma unroll
        for (int half = 0; half < 2; half++) {
            int mi = m0 + warpM * 32 + mt * 16 + gid + half * 8;
            float rowsum = 0.f;
#pragma unroll
            for (int nt = 0; nt < 8; nt++) {
                int n = n0 + warpN * 64 + nt * 8 + 2 * tig;
                float2 pv = *(const float2*)&prevb[(size_t)mi * 1024 + n];
                float2 mk = *(const float2*)&mask[(size_t)mi * 1024 + n];
                float2 r;
                r.x = acc[mt][nt][half * 2 + 0] * 0.03125f + pv.x + mk.x;
                r.y = acc[mt][nt][half * 2 + 1] * 0.03125f + pv.y + mk.y;
                *(float2*)&outb[(size_t)mi * 1024 + n] = r;
                rowsum += __expf(r.x) + __expf(r.y);
            }
            rowsum += __shfl_xor_sync(0xffffffffu, rowsum, 1);
            rowsum += __shfl_xor_sync(0xffffffffu, rowsum, 2);
            if (tig == 0)
                g_psum[((size_t)bh * 1024 + mi) * 16 + blockIdx.y * 2 + warpN] = rowsum;
        }
}

// ---------------- A = softmax(S) @ V  (exp w/o max; V 3-stage cp.async; 1 sync/iter) ------
// dyn smem: As 2 x SLAB_M, Bs 3 x SLAB_K
__global__ __launch_bounds__(256, 2) void gemm_pv_t(const float* __restrict__ S) {
    const int m0 = blockIdx.x * 128;
    const int bh = blockIdx.y;
    const int b4 = bh >> 3, head = bh & 7;
    const float* Sb = S + ((size_t)bh << 20);
    const float* Vb = g_t[2][b4] + head * 128;
    float* Ab = g_a[b4];

    extern __shared__ __align__(16) float sh[];
    float* ABUF[2] = {sh, sh + SLAB_M};
    float* BBUF[3] = {sh + 2 * SLAB_M, sh + 2 * SLAB_M + SLAB_K, sh + 2 * SLAB_M + 2 * SLAB_K};
    const int tid = threadIdx.x;
    const int lane = tid & 31, warp = tid >> 5, warpM = warp & 3, warpN = warp >> 2;
    const int gid = lane >> 2, tig = lane & 3;

    const int arow = tid >> 1;     // local m row this thread stages
    const int aq = (tid & 1) * 8;  // k offset within slab
    const float* Srow = Sb + (size_t)(m0 + arow) * 1024;

    // row normalizer from the 16 deterministic partials
    float rsum = 0.f;
    {
        const float* ps = &g_psum[((size_t)bh * 1024 + m0 + arow) * 16];
#pragma unroll
        for (int i = 0; i < 16; i++) rsum += ps[i];
    }
    const float rv = 1.0f / rsum;

    float acc[2][8][4] = {};
    float4 pa0 = *(const float4*)&Srow[aq];
    float4 pa1 = *(const float4*)&Srow[aq + 4];

    copy_kmaj(BBUF[0], Vb, tid);
    CP_COMMIT;
    copy_kmaj(BBUF[1], Vb + (size_t)16 * 1024, tid);
    CP_COMMIT;

    for (int it = 0; it < 64; it++) {
        const int c2 = it & 1;
        CP_WAIT1;
        {
            float* dst = &ABUF[c2][arow * STR_M + aq];
            dst[0] = __expf(pa0.x) * rv;
            dst[1] = __expf(pa0.y) * rv;
            dst[2] = __expf(pa0.z) * rv;
            dst[3] = __expf(pa0.w) * rv;
            dst[4] = __expf(pa1.x) * rv;
            dst[5] = __expf(pa1.y) * rv;
            dst[6] = __expf(pa1.z) * rv;
            dst[7] = __expf(pa1.w) * rv;
        }
        if (it + 1 < 64) {
            pa0 = *(const float4*)&Srow[(it + 1) * 16 + aq];
            pa1 = *(const float4*)&Srow[(it + 1) * 16 + aq + 4];
        }
        __syncthreads();
        if (it + 2 < 64) copy_kmaj(BBUF[(it + 2) % 3], Vb + (size_t)(it + 2) * 16 * 1024, tid);
        CP_COMMIT;
        frag_compute<false, true>(ABUF[c2], BBUF[it % 3], acc, gid, tig, warpM, warpN);
    }

#pragma unroll
    for (int mt = 0; mt < 2; mt++)
#pragma unroll
        for (int half = 0; half < 2; half++) {
            int mi = m0 + warpM * 32 + mt * 16 + gid + half * 8;
#pragma unroll
            for (int nt = 0; nt < 8; nt++) {
                int n = warpN * 64 + nt * 8 + 2 * tig;
                float2 r = make_float2(acc[mt][nt][half * 2 + 0], acc[mt][nt][half * 2 + 1]);
                *(float2*)&Ab[(size_t)mi * 1024 + head * 128 + n] = r;
            }
        }
}

// ---------------- 4x4 depthwise channel mix ----------------
__global__ __launch_bounds__(256) void dw_kernel(const float* __restrict__ dw) {
    int idx = blockIdx.x * 256 + threadIdx.x;
    int b = idx >> 18;
    size_t off = ((size_t)(idx & 262143)) << 2;
    float4 a[4];
#pragma unroll
    for (int c = 0; c < 4; c++) a[c] = *(const float4*)&g_a[b * 4 + c][off];
#pragma unroll
    for (int o = 0; o < 4; o++) {
        float w0 = dw[o * 4 + 0], w1 = dw[o * 4 + 1], w2 = dw[o * 4 + 2], w3 = dw[o * 4 + 3];
        float4 r;
        r.x = w0 * a[0].x + w1 * a[1].x + w2 * a[2].x + w3 * a[3].x;
        r.y = w0 * a[0].y + w1 * a[1].y + w2 * a[2].y + w3 * a[3].y;
        r.z = w0 * a[0].z + w1 * a[1].z + w2 * a[2].z + w3 * a[3].z;
        r.w = w0 * a[0].w + w1 * a[1].w + w2 * a[2].w + w3 * a[3].w;
        *(float4*)&g_ao[b * 4 + o][off] = r;
    }
}

// ---------------- wo_pw: Out[f,w] = sum_h Wt[f,h] * AoT[w,h] ----------------
// dyn smem: As/Bs 3 x SLAB_M each
__global__ __launch_bounds__(256, 2) void gemm_wo_t(const float* __restrict__ Wopw) {
    const int m0 = blockIdx.x * 128;  // f
    const int n0 = blockIdx.y * 128;  // w
    const int b4 = blockIdx.z;
    const int am = b4 & 3;
    const float* Wt = Wopw + ((size_t)am << 20);
    const float* Ao = g_ao[b4];
    float* Out = g_a2[b4];

    extern __shared__ __align__(16) float sh[];
    float* ABUF[3] = {sh, sh + SLAB_M, sh + 2 * SLAB_M};
    float* BBUF[3] = {sh + 3 * SLAB_M, sh + 4 * SLAB_M, sh + 5 * SLAB_M};
    const int tid = threadIdx.x;
    const int lane = tid & 31, warp = tid >> 5, warpM = warp & 3, warpN = warp >> 2;
    const int gid = lane >> 2, tig = lane & 3;

    float acc[2][8][4] = {};

    copy_mmaj(ABUF[0], Wt + (size_t)m0 * 1024, tid);
    copy_mmaj(BBUF[0], Ao + (size_t)n0 * 1024, tid);
    CP_COMMIT;
    copy_mmaj(ABUF[1], Wt + (size_t)m0 * 1024 + 16, tid);
    copy_mmaj(BBUF[1], Ao + (size_t)n0 * 1024 + 16, tid);
    CP_COMMIT;

    for (int it = 0; it < 64; it++) {
        CP_WAIT1;
        __syncthreads();
        if (it + 2 < 64) {
            int nx = (it + 2) % 3;
            copy_mmaj(ABUF[nx], Wt + (size_t)m0 * 1024 + (it + 2) * 16, tid);
            copy_mmaj(BBUF[nx], Ao + (size_t)n0 * 1024 + (it + 2) * 16, tid);
        }
        CP_COMMIT;
        frag_compute<false, false>(ABUF[it % 3], BBUF[it % 3], acc, gid, tig, warpM, warpN);
    }

#pragma unroll
    for (int mt = 0; mt < 2; mt++)
#pragma unroll
        for (int half = 0; half < 2; half++) {
            int mi = m0 + warpM * 32 + mt * 16 + gid + half * 8;
#pragma unroll
            for (int nt = 0; nt < 8; nt++) {
                int n = n0 + warpN * 64 + nt * 8 + 2 * tig;
                float2 r = make_float2(acc[mt][nt][half * 2 + 0], acc[mt][nt][half * 2 + 1]);
                *(float2*)&Out[(size_t)mi * 1024 + n] = r;
            }
        }
}

// ---------------- final conv 3x3 over concat(x[16], a2[4]) -> 16 channels ----------------
__global__ __launch_bounds__(256) void conv_out_kernel(const float* __restrict__ x,
                                                       const float* __restrict__ wo,
                                                       const float* __restrict__ bo,
                                                       float* __restrict__ out) {
    __shared__ float sx[4][18][68];
    __shared__ float sw[16 * 20 * 9];
    const int b = blockIdx.x;
    const int h0 = blockIdx.y * 16;
    const int w0 = blockIdx.z * 64;
    const int tx = threadIdx.x, ty = threadIdx.y;
    const int tid = ty * 16 + tx;

    for (int i = tid; i < 2880; i += 256) sw[i] = wo[i];

    float acc[16][4];
#pragma unroll
    for (int o = 0; o < 16; o++)
#pragma unroll
        for (int p = 0; p < 4; p++) acc[o][p] = 0.f;

    for (int cc = 0; cc < 20; cc += 4) {
        __syncthreads();
        for (int e = tid; e < 4 * 18 * 66; e += 256) {
            int ch = e / (18 * 66);
            int r = (e / 66) % 18;
            int cl = e % 66;
            int gh = h0 + r - 1, gw = w0 + cl - 1;
            int c = cc + ch;
            float v = 0.f;
            if ((unsigned)gh < 1024u && (unsigned)gw < 1024u) {
                const float* src = (c < 16) ? (x + (((size_t)(b * 16 + c)) << 20))
                                            : g_a2[b * 4 + (c - 16)];
                v = src[gh * 1024 + gw];
            }
            sx[ch][r][cl] = v;
        }
        __syncthreads();
#pragma unroll
        for (int ch = 0; ch < 4; ch++) {
#pragma unroll
            for (int dy = 0; dy < 3; dy++) {
                float xr[6];
#pragma unroll
                for (int i = 0; i < 6; i++) xr[i] = sx[ch][ty + dy][tx * 4 + i];
#pragma unroll
                for (int dx = 0; dx < 3; dx++) {
                    int widx = (cc + ch) * 9 + dy * 3 + dx;
#pragma unroll
                    for (int o = 0; o < 16; o++) {
                        float wv_ = sw[o * 180 + widx];
#pragma unroll
                        for (int p = 0; p < 4; p++) acc[o][p] += wv_ * xr[p + dx];
                    }
                }
            }
        }
    }

    int gh = h0 + ty, gw = w0 + tx * 4;
#pragma unroll
    for (int o = 0; o < 16; o++) {
        float bb = bo[o];
        float4 v = make_float4(acc[o][0] + bb, acc[o][1] + bb, acc[o][2] + bb, acc[o][3] + bb);
        *(float4*)&out[(((size_t)(b * 16 + o)) << 20) + gh * 1024 + gw] = v;
    }
}

// ---------------- launch ----------------
extern "C" void kernel_launch(void* const* d_in, const int* in_sizes, int n_in,
                              void* d_out, int out_size) {
    const float* x       = (const float*)d_in[0];
    const float* prev_qk = (const float*)d_in[1];
    const float* mask    = (const float*)d_in[2];
    const float* wq_conv = (const float*)d_in[3];
    const float* bq_conv = (const float*)d_in[4];
    const float* wq_pw   = (const float*)d_in[5];
    const float* wk_conv = (const float*)d_in[6];
    const float* bk_conv = (const float*)d_in[7];
    const float* wk_pw   = (const float*)d_in[8];
    const float* wv_conv = (const float*)d_in[9];
    const float* bv_conv = (const float*)d_in[10];
    const float* wv_pw   = (const float*)d_in[11];
    const float* wo_pw   = (const float*)d_in[12];
    const float* wo_dw   = (const float*)d_in[13];
    const float* wo_conv = (const float*)d_in[14];
    const float* bo_conv = (const float*)d_in[15];

    float* outp = (float*)d_out;                       // (2,16,1024,1024)
    float* qk_out = outp + (size_t)NB * NC * NF * NW;  // (2,4,8,1024,1024)

    const int PW_SM = (3 * SLAB_K + 3 * SLAB_M) * 4;   // 56832
    const int MM_SM = (6 * SLAB_M) * 4;                // 61440
    const int PV_SM = (2 * SLAB_M + 3 * SLAB_K) * 4;   // 46592

    cudaFuncSetAttribute(gemm_pw_t, cudaFuncAttributeMaxDynamicSharedMemorySize, PW_SM);
    cudaFuncSetAttribute(gemm_qk_t, cudaFuncAttributeMaxDynamicSharedMemorySize, MM_SM);
    cudaFuncSetAttribute(gemm_wo_t, cudaFuncAttributeMaxDynamicSharedMemorySize, MM_SM);
    cudaFuncSetAttribute(gemm_pv_t, cudaFuncAttributeMaxDynamicSharedMemorySize, PV_SM);

    rope_init_kernel<<<64, 1024>>>();
    conv_qkv_kernel<<<dim3(NB, 64, 16), dim3(16, 16)>>>(x, wq_conv, bq_conv,
                                                        wk_conv, bk_conv, wv_conv, bv_conv);
    gemm_pw_t<<<dim3(8, 8, 8), 256, PW_SM>>>(wq_pw, 0, 1);
    gemm_pw_t<<<dim3(8, 8, 8), 256, PW_SM>>>(wk_pw, 1, 1);
    gemm_pw_t<<<dim3(8, 8, 8), 256, PW_SM>>>(wv_pw, 2, 0);
    gemm_qk_t<<<dim3(8, 8, 64), 256, MM_SM>>>(prev_qk, mask, qk_out);
    gemm_pv_t<<<dim3(8, 64), 256, PV_SM>>>(qk_out);
    dw_kernel<<<2048, 256>>>(wo_dw);
    gemm_wo_t<<<dim3(8, 8, 8), 256, MM_SM>>>(wo_pw);
    conv_out_kernel<<<dim3(NB, 64, 16), dim3(16, 16)>>>(x, wo_conv, bo_conv, outp);
}

// round 5
// speedup vs baseline: 1.0761x; 1.0761x over previous
#include <cuda_runtime.h>
#include <math.h>

// Problem dims
#define NB 2
#define NC 16
#define NAM 4
#define NHEADS 8
#define NF 1024
#define NW 1024
#define NHD 128

#define BKDIM 16
#define STR_K 136  // k-major smem stride (words)
#define STR_M 20   // m-major smem stride (words); (20*L)%32 all-distinct -> LDSM conflict-free
#define SLAB_K (BKDIM * STR_K)   // 2176
#define SLAB_M (128 * STR_M)     // 2560

// ---------------- scratch (device globals; no runtime allocation) ----------------
__device__ float g_y[3][8][NF * NW];     // conv outputs for q,k,v   [tensor][b*4+am][h*1024+w]
__device__ float g_t[3][8][NW * NF];     // qT,kT,vT                 [tensor][b*4+am][w*1024+f]
__device__ float g_a[8][NW * NF];        // attention out            [b*4+am][w*1024+f]
__device__ float g_ao[8][NW * NF];       // after dw channel mix     [b*4+am][w*1024+h]
__device__ float g_a2[8][NF * NW];       // after wo_pw              [b*4+am][f*1024+w]
__device__ float g_psum[64 * 1024 * 16]; // per-row exp partial sums [bh*1024+row][16]
__device__ float g_cos[NW * (NHD / 2)];
__device__ float g_sin[NW * (NHD / 2)];

// ---------------- helpers ----------------
__device__ __forceinline__ unsigned sptr(const void* p) {
    return (unsigned)__cvta_generic_to_shared(p);
}
__device__ __forceinline__ void cpasync16(const void* dst_smem, const void* src_gmem) {
    asm volatile("cp.async.cg.shared.global [%0], [%1], 16;" ::"r"(sptr(dst_smem)),
                 "l"(src_gmem));
}
#define CP_COMMIT asm volatile("cp.async.commit_group;")
#define CP_WAIT0 asm volatile("cp.async.wait_group 0;")

__device__ __forceinline__ void ldsm_x4(unsigned r[4], const void* p) {
    asm volatile("ldmatrix.sync.aligned.m8n8.x4.shared.b16 {%0,%1,%2,%3}, [%4];"
                 : "=r"(r[0]), "=r"(r[1]), "=r"(r[2]), "=r"(r[3])
                 : "r"(sptr(p)));
}

__device__ __forceinline__ void mma_tf32(float* c, unsigned a0, unsigned a1, unsigned a2,
                                         unsigned a3, unsigned b0, unsigned b1) {
    asm volatile(
        "mma.sync.aligned.m16n8k8.row.col.f32.tf32.tf32.f32 "
        "{%0,%1,%2,%3}, {%4,%5,%6,%7}, {%8,%9}, {%0,%1,%2,%3};"
        : "+f"(c[0]), "+f"(c[1]), "+f"(c[2]), "+f"(c[3])
        : "r"(a0), "r"(a1), "r"(a2), "r"(a3), "r"(b0), "r"(b1));
}

// ---- fragment compute over one 16-k slab; 128x128 C tile, 8 warps 4(M)x2(N) ----
// A m-major LDSM + B m-major LDSM
__device__ __forceinline__ void fc_mm(const float* As, const float* Bs, float (&acc)[2][8][4],
                                      int lane, int warpM, int warpN) {
    const int la = lane & 15, ha = (lane >> 4) * 4;
    const int lb = lane & 7, hb = (lane >> 3) * 4;
    unsigned a[2][2][4];
#pragma unroll
    for (int mt = 0; mt < 2; mt++)
#pragma unroll
        for (int kk = 0; kk < 2; kk++)
            ldsm_x4(a[mt][kk], &As[(warpM * 32 + mt * 16 + la) * STR_M + kk * 8 + ha]);
#pragma unroll
    for (int nh = 0; nh < 2; nh++) {
        unsigned b[4][4];
#pragma unroll
        for (int j = 0; j < 4; j++)
            ldsm_x4(b[j], &Bs[(warpN * 64 + nh * 32 + j * 8 + lb) * STR_M + hb]);
#pragma unroll
        for (int kk = 0; kk < 2; kk++)
#pragma unroll
            for (int mt = 0; mt < 2; mt++)
#pragma unroll
                for (int j = 0; j < 4; j++)
                    mma_tf32(acc[mt][nh * 4 + j], a[mt][kk][0], a[mt][kk][1], a[mt][kk][2],
                             a[mt][kk][3], b[j][kk * 2], b[j][kk * 2 + 1]);
    }
}

// A k-major scalar + B m-major LDSM  (pw)
__device__ __forceinline__ void fc_km(const float* As, const float* Bs, float (&acc)[2][8][4],
                                      int lane, int warpM, int warpN) {
    const int gid = lane >> 2, tig = lane & 3;
    const int lb = lane & 7, hb = (lane >> 3) * 4;
    unsigned a[2][2][4];
#pragma unroll
    for (int kk = 0; kk < 2; kk++) {
        const int k = kk * 8;
#pragma unroll
        for (int mt = 0; mt < 2; mt++) {
            int rb = warpM * 32 + mt * 16 + gid;
            a[mt][kk][0] = __float_as_uint(As[(k + tig) * STR_K + rb]);
            a[mt][kk][1] = __float_as_uint(As[(k + tig) * STR_K + rb + 8]);
            a[mt][kk][2] = __float_as_uint(As[(k + 4 + tig) * STR_K + rb]);
            a[mt][kk][3] = __float_as_uint(As[(k + 4 + tig) * STR_K + rb + 8]);
        }
    }
#pragma unroll
    for (int nh = 0; nh < 2; nh++) {
        unsigned b[4][4];
#pragma unroll
        for (int j = 0; j < 4; j++)
            ldsm_x4(b[j], &Bs[(warpN * 64 + nh * 32 + j * 8 + lb) * STR_M + hb]);
#pragma unroll
        for (int kk = 0; kk < 2; kk++)
#pragma unroll
            for (int mt = 0; mt < 2; mt++)
#pragma unroll
                for (int j = 0; j < 4; j++)
                    mma_tf32(acc[mt][nh * 4 + j], a[mt][kk][0], a[mt][kk][1], a[mt][kk][2],
                             a[mt][kk][3], b[j][kk * 2], b[j][kk * 2 + 1]);
    }
}

// A m-major LDSM + B k-major scalar  (pv)
__device__ __forceinline__ void fc_mk(const float* As, const float* Bs, float (&acc)[2][8][4],
                                      int lane, int warpM, int warpN) {
    const int la = lane & 15, ha = (lane >> 4) * 4;
    const int gid = lane >> 2, tig = lane & 3;
    unsigned a[2][2][4];
#pragma unroll
    for (int mt = 0; mt < 2; mt++)
#pragma unroll
        for (int kk = 0; kk < 2; kk++)
            ldsm_x4(a[mt][kk], &As[(warpM * 32 + mt * 16 + la) * STR_M + kk * 8 + ha]);
#pragma unroll
    for (int kk = 0; kk < 2; kk++) {
        const int k = kk * 8;
        unsigned bf[8][2];
#pragma unroll
        for (int nt = 0; nt < 8; nt++) {
            int cb = warpN * 64 + nt * 8 + gid;
            bf[nt][0] = __float_as_uint(Bs[(k + tig) * STR_K + cb]);
            bf[nt][1] = __float_as_uint(Bs[(k + 4 + tig) * STR_K + cb]);
        }
#pragma unroll
        for (int mt = 0; mt < 2; mt++)
#pragma unroll
            for (int nt = 0; nt < 8; nt++)
                mma_tf32(acc[mt][nt], a[mt][kk][0], a[mt][kk][1], a[mt][kk][2], a[mt][kk][3],
                         bf[nt][0], bf[nt][1]);
    }
}

// copy one 16(k) x 128(mn) k-major slab
__device__ __forceinline__ void copy_kmaj(float* buf, const float* src, int tid) {
#pragma unroll
    for (int i = 0; i < 2; i++) {
        int idx = tid + i * 256;
        int row = idx >> 5, c = (idx & 31) * 4;
        cpasync16(&buf[row * STR_K + c], &src[(size_t)row * 1024 + c]);
    }
}
// copy one 128(mn) x 16(k) m-major slab
__device__ __forceinline__ void copy_mmaj(float* buf, const float* src, int tid) {
#pragma unroll
    for (int i = 0; i < 2; i++) {
        int idx = tid + i * 256;
        int row = idx >> 2, c = (idx & 3) * 4;
        cpasync16(&buf[row * STR_M + c], &src[(size_t)row * 1024 + c]);
    }
}

// ---------------- RoPE table init ----------------
__global__ void rope_init_kernel() {
    int idx = blockIdx.x * blockDim.x + threadIdx.x;
    if (idx >= NW * 64) return;
    int w = idx >> 6, j = idx & 63;
    double inv = exp(-((double)(2 * j) / (double)NHD) * log(10000.0));
    double ang = (double)w * inv;
    g_cos[idx] = (float)cos(ang);
    g_sin[idx] = (float)sin(ang);
}

// ---------------- conv 3x3 (16 -> 4) producing q,k,v conv outputs in one pass ----------------
__global__ __launch_bounds__(256) void conv_qkv_kernel(
    const float* __restrict__ x,
    const float* __restrict__ wq, const float* __restrict__ bq,
    const float* __restrict__ wk, const float* __restrict__ bk,
    const float* __restrict__ wv, const float* __restrict__ bv) {
    __shared__ float sx[4][18][68];
    __shared__ float sw[3 * 4 * 16 * 9];
    const int b = blockIdx.x;
    const int h0 = blockIdx.y * 16;
    const int w0 = blockIdx.z * 64;
    const int tx = threadIdx.x, ty = threadIdx.y;
    const int tid = ty * 16 + tx;

    for (int i = tid; i < 576; i += 256) {
        sw[i] = wq[i];
        sw[576 + i] = wk[i];
        sw[1152 + i] = wv[i];
    }

    float acc[12][4];
#pragma unroll
    for (int o = 0; o < 12; o++)
#pragma unroll
        for (int p = 0; p < 4; p++) acc[o][p] = 0.f;

    for (int cc = 0; cc < 16; cc += 4) {
        __syncthreads();
        for (int e = tid; e < 4 * 18 * 66; e += 256) {
            int ch = e / (18 * 66);
            int r = (e / 66) % 18;
            int cl = e % 66;
            int gh = h0 + r - 1, gw = w0 + cl - 1;
            float v = 0.f;
            if ((unsigned)gh < 1024u && (unsigned)gw < 1024u)
                v = x[(((size_t)(b * 16 + cc + ch)) << 20) + gh * 1024 + gw];
            sx[ch][r][cl] = v;
        }
        __syncthreads();
#pragma unroll
        for (int ch = 0; ch < 4; ch++) {
#pragma unroll
            for (int dy = 0; dy < 3; dy++) {
                float xr[6];
#pragma unroll
                for (int i = 0; i < 6; i++) xr[i] = sx[ch][ty + dy][tx * 4 + i];
#pragma unroll
                for (int dx = 0; dx < 3; dx++) {
                    int widx = (cc + ch) * 9 + dy * 3 + dx;
#pragma unroll
                    for (int o = 0; o < 12; o++) {
                        float wv_ = sw[(o >> 2) * 576 + (o & 3) * 144 + widx];
#pragma unroll
                        for (int p = 0; p < 4; p++) acc[o][p] += wv_ * xr[p + dx];
                    }
                }
            }
        }
    }

    int gh = h0 + ty, gw = w0 + tx * 4;
#pragma unroll
    for (int t = 0; t < 3; t++) {
        const float* bias = (t == 0) ? bq : (t == 1) ? bk : bv;
#pragma unroll
        for (int m = 0; m < 4; m++) {
            float bb = bias[m];
            float4 v = make_float4(acc[t * 4 + m][0] + bb, acc[t * 4 + m][1] + bb,
                                   acc[t * 4 + m][2] + bb, acc[t * 4 + m][3] + bb);
            *(float4*)&g_y[t][b * 4 + m][gh * 1024 + gw] = v;
        }
    }
}

// ---------------- pw linear: OutT[w,f] = sum_h Wt[f,h] * Y[h,w]; optional RoPE ----------------
__global__ __launch_bounds__(256, 2) void gemm_pw_t(const float* __restrict__ Wpw, int t,
                                                    int do_rope) {
    const int m0 = blockIdx.x * 128;  // w
    const int n0 = blockIdx.y * 128;  // f
    const int b4 = blockIdx.z;
    const int am = b4 & 3;
    const float* Y = g_y[t][b4];
    const float* Wt = Wpw + ((size_t)am << 20);
    float* Out = g_t[t][b4];

    __shared__ __align__(16) float As[2][SLAB_K];  // k-major
    __shared__ __align__(16) float Bs[2][SLAB_M];  // n-major
    const int tid = threadIdx.x;
    const int lane = tid & 31, warp = tid >> 5, warpM = warp & 3, warpN = warp >> 2;
    const int gid = lane >> 2, tig = lane & 3;

    float acc[2][8][4] = {};

    copy_kmaj(As[0], Y + m0, tid);
    copy_mmaj(Bs[0], Wt + (size_t)n0 * 1024, tid);
    CP_COMMIT;

    for (int it = 0; it < 64; it++) {
        const int cur = it & 1;
        CP_WAIT0;
        __syncthreads();
        if (it + 1 < 64) {
            copy_kmaj(As[cur ^ 1], Y + (size_t)(it + 1) * 16 * 1024 + m0, tid);
            copy_mmaj(Bs[cur ^ 1], Wt + (size_t)n0 * 1024 + (it + 1) * 16, tid);
            CP_COMMIT;
        }
        fc_km(As[cur], Bs[cur], acc, lane, warpM, warpN);
    }

#pragma unroll
    for (int mt = 0; mt < 2; mt++)
#pragma unroll
        for (int half = 0; half < 2; half++) {
            int w = m0 + warpM * 32 + mt * 16 + gid + half * 8;
#pragma unroll
            for (int nt = 0; nt < 8; nt++) {
                int f = n0 + warpN * 64 + nt * 8 + 2 * tig;
                float v0 = acc[mt][nt][half * 2 + 0];
                float v1 = acc[mt][nt][half * 2 + 1];
                if (do_rope) {
                    int j0 = (f >> 1) & 63;
                    float c = g_cos[w * 64 + j0], s = g_sin[w * 64 + j0];
                    float e = v0 * c - v1 * s, o = v1 * c + v0 * s;
                    v0 = e;
                    v1 = o;
                }
                *(float2*)&Out[(size_t)w * 1024 + f] = make_float2(v0, v1);
            }
        }
}

// ---------------- S = q k^T / 32 + prev_qk + mask; fused per-row exp partial sums ----------
__global__ __launch_bounds__(256, 2) void gemm_qk_t(const float* __restrict__ prev_qk,
                                                    const float* __restrict__ mask,
                                                    float* __restrict__ qk_out) {
    const int m0 = blockIdx.x * 128;
    const int n0 = blockIdx.y * 128;
    const int bh = blockIdx.z;
    const int b4 = bh >> 3, head = bh & 7;
    const float* Qb = g_t[0][b4] + head * 128;
    const float* Kb = g_t[1][b4] + head * 128;

    __shared__ __align__(16) float As[2][SLAB_M];
    __shared__ __align__(16) float Bs[2][SLAB_M];
    const int tid = threadIdx.x;
    const int lane = tid & 31, warp = tid >> 5, warpM = warp & 3, warpN = warp >> 2;
    const int gid = lane >> 2, tig = lane & 3;

    float acc[2][8][4] = {};

    copy_mmaj(As[0], Qb + (size_t)m0 * 1024, tid);
    copy_mmaj(Bs[0], Kb + (size_t)n0 * 1024, tid);
    CP_COMMIT;

    for (int it = 0; it < 8; it++) {
        const int cur = it & 1;
        CP_WAIT0;
        __syncthreads();
        if (it + 1 < 8) {
            copy_mmaj(As[cur ^ 1], Qb + (size_t)m0 * 1024 + (it + 1) * 16, tid);
            copy_mmaj(Bs[cur ^ 1], Kb + (size_t)n0 * 1024 + (it + 1) * 16, tid);
            CP_COMMIT;
        }
        fc_mm(As[cur], Bs[cur], acc, lane, warpM, warpN);
    }

    const float* prevb = prev_qk + ((size_t)bh << 20);
    float* outb = qk_out + ((size_t)bh << 20);
#pragma unroll
    for (int mt = 0; mt < 2; mt++)
#pragma unroll
        for (int half = 0; half < 2; half++) {
            int mi = m0 + warpM * 32 + mt * 16 + gid + half * 8;
            float rowsum = 0.f;
#pragma unroll
            for (int nt = 0; nt < 8; nt++) {
                int n = n0 + warpN * 64 + nt * 8 + 2 * tig;
                float2 pv = *(const float2*)&prevb[(size_t)mi * 1024 + n];
                float2 mk = *(const float2*)&mask[(size_t)mi * 1024 + n];
                float2 r;
                r.x = acc[mt][nt][half * 2 + 0] * 0.03125f + pv.x + mk.x;
                r.y = acc[mt][nt][half * 2 + 1] * 0.03125f + pv.y + mk.y;
                *(float2*)&outb[(size_t)mi * 1024 + n] = r;
                rowsum += __expf(r.x) + __expf(r.y);
            }
            rowsum += __shfl_xor_sync(0xffffffffu, rowsum, 1);
            rowsum += __shfl_xor_sync(0xffffffffu, rowsum, 2);
            if (tig == 0)
                g_psum[((size_t)bh * 1024 + mi) * 16 + blockIdx.y * 2 + warpN] = rowsum;
        }
}

// ---------------- A = softmax(S) @ V  (exp w/o max; normalizer from g_psum) ----------------
__global__ __launch_bounds__(256, 2) void gemm_pv_t(const float* __restrict__ S) {
    const int m0 = blockIdx.x * 128;
    const int bh = blockIdx.y;
    const int b4 = bh >> 3, head = bh & 7;
    const float* Sb = S + ((size_t)bh << 20);
    const float* Vb = g_t[2][b4] + head * 128;
    float* Ab = g_a[b4];

    __shared__ __align__(16) float As[2][SLAB_M];  // m-major P tile
    __shared__ __align__(16) float Bs[2][SLAB_K];  // k-major V tile
    const int tid = threadIdx.x;
    const int lane = tid & 31, warp = tid >> 5, warpM = warp & 3, warpN = warp >> 2;
    const int gid = lane >> 2, tig = lane & 3;

    const int arow = tid >> 1;     // local m row this thread stages
    const int aq = (tid & 1) * 8;  // k offset within slab
    const float* Srow = Sb + (size_t)(m0 + arow) * 1024;

    float rsum = 0.f;
    {
        const float* ps = &g_psum[((size_t)bh * 1024 + m0 + arow) * 16];
#pragma unroll
        for (int i = 0; i < 16; i++) rsum += ps[i];
    }
    const float rv = 1.0f / rsum;

    float acc[2][8][4] = {};
    float4 pa0 = *(const float4*)&Srow[aq];
    float4 pa1 = *(const float4*)&Srow[aq + 4];

    copy_kmaj(Bs[0], Vb, tid);
    CP_COMMIT;

    for (int it = 0; it < 64; it++) {
        const int cur = it & 1;
        CP_WAIT0;
        __syncthreads();
        {
            float* dst = &As[cur][arow * STR_M + aq];
            dst[0] = __expf(pa0.x) * rv;
            dst[1] = __expf(pa0.y) * rv;
            dst[2] = __expf(pa0.z) * rv;
            dst[3] = __expf(pa0.w) * rv;
            dst[4] = __expf(pa1.x) * rv;
            dst[5] = __expf(pa1.y) * rv;
            dst[6] = __expf(pa1.z) * rv;
            dst[7] = __expf(pa1.w) * rv;
        }
        if (it + 1 < 64) {
            pa0 = *(const float4*)&Srow[(it + 1) * 16 + aq];
            pa1 = *(const float4*)&Srow[(it + 1) * 16 + aq + 4];
            copy_kmaj(Bs[cur ^ 1], Vb + (size_t)(it + 1) * 16 * 1024, tid);
            CP_COMMIT;
        }
        __syncthreads();
        fc_mk(As[cur], Bs[cur], acc, lane, warpM, warpN);
    }

#pragma unroll
    for (int mt = 0; mt < 2; mt++)
#pragma unroll
        for (int half = 0; half < 2; half++) {
            int mi = m0 + warpM * 32 + mt * 16 + gid + half * 8;
#pragma unroll
            for (int nt = 0; nt < 8; nt++) {
                int n = warpN * 64 + nt * 8 + 2 * tig;
                float2 r = make_float2(acc[mt][nt][half * 2 + 0], acc[mt][nt][half * 2 + 1]);
                *(float2*)&Ab[(size_t)mi * 1024 + head * 128 + n] = r;
            }
        }
}

// ---------------- 4x4 depthwise channel mix ----------------
__global__ __launch_bounds__(256) void dw_kernel(const float* __restrict__ dw) {
    int idx = blockIdx.x * 256 + threadIdx.x;
    int b = idx >> 18;
    size_t off = ((size_t)(idx & 262143)) << 2;
    float4 a[4];
#pragma unroll
    for (int c = 0; c < 4; c++) a[c] = *(const float4*)&g_a[b * 4 + c][off];
#pragma unroll
    for (int o = 0; o < 4; o++) {
        float w0 = dw[o * 4 + 0], w1 = dw[o * 4 + 1], w2 = dw[o * 4 + 2], w3 = dw[o * 4 + 3];
        float4 r;
        r.x = w0 * a[0].x + w1 * a[1].x + w2 * a[2].x + w3 * a[3].x;
        r.y = w0 * a[0].y + w1 * a[1].y + w2 * a[2].y + w3 * a[3].y;
        r.z = w0 * a[0].z + w1 * a[1].z + w2 * a[2].z + w3 * a[3].z;
        r.w = w0 * a[0].w + w1 * a[1].w + w2 * a[2].w + w3 * a[3].w;
        *(float4*)&g_ao[b * 4 + o][off] = r;
    }
}

// ---------------- wo_pw: Out[f,w] = sum_h Wt[f,h] * AoT[w,h] ----------------
__global__ __launch_bounds__(256, 2) void gemm_wo_t(const float* __restrict__ Wopw) {
    const int m0 = blockIdx.x * 128;  // f
    const int n0 = blockIdx.y * 128;  // w
    const int b4 = blockIdx.z;
    const int am = b4 & 3;
    const float* Wt = Wopw + ((size_t)am << 20);
    const float* Ao = g_ao[b4];
    float* Out = g_a2[b4];

    __shared__ __align__(16) float As[2][SLAB_M];
    __shared__ __align__(16) float Bs[2][SLAB_M];
    const int tid = threadIdx.x;
    const int lane = tid & 31, warp = tid >> 5, warpM = warp & 3, warpN = warp >> 2;
    const int gid = lane >> 2, tig = lane & 3;

    float acc[2][8][4] = {};

    copy_mmaj(As[0], Wt + (size_t)m0 * 1024, tid);
    copy_mmaj(Bs[0], Ao + (size_t)n0 * 1024, tid);
    CP_COMMIT;

    for (int it = 0; it < 64; it++) {
        const int cur = it & 1;
        CP_WAIT0;
        __syncthreads();
        if (it + 1 < 64) {
            copy_mmaj(As[cur ^ 1], Wt + (size_t)m0 * 1024 + (it + 1) * 16, tid);
            copy_mmaj(Bs[cur ^ 1], Ao + (size_t)n0 * 1024 + (it + 1) * 16, tid);
            CP_COMMIT;
        }
        fc_mm(As[cur], Bs[cur], acc, lane, warpM, warpN);
    }

#pragma unroll
    for (int mt = 0; mt < 2; mt++)
#pragma unroll
        for (int half = 0; half < 2; half++) {
            int mi = m0 + warpM * 32 + mt * 16 + gid + half * 8;
#pragma unroll
            for (int nt = 0; nt < 8; nt++) {
                int n = n0 + warpN * 64 + nt * 8 + 2 * tig;
                float2 r = make_float2(acc[mt][nt][half * 2 + 0], acc[mt][nt][half * 2 + 1]);
                *(float2*)&Out[(size_t)mi * 1024 + n] = r;
            }
        }
}

// ---------------- final conv 3x3 over concat(x[16], a2[4]) -> 16 channels ----------------
__global__ __launch_bounds__(256) void conv_out_kernel(const float* __restrict__ x,
                                                       const float* __restrict__ wo,
                                                       const float* __restrict__ bo,
                                                       float* __restrict__ out) {
    __shared__ float sx[4][18][68];
    __shared__ float sw[16 * 20 * 9];
    const int b = blockIdx.x;
    const int h0 = blockIdx.y * 16;
    const int w0 = blockIdx.z * 64;
    const int tx = threadIdx.x, ty = threadIdx.y;
    const int tid = ty * 16 + tx;

    for (int i = tid; i < 2880; i += 256) sw[i] = wo[i];

    float acc[16][4];
#pragma unroll
    for (int o = 0; o < 16; o++)
#pragma unroll
        for (int p = 0; p < 4; p++) acc[o][p] = 0.f;

    for (int cc = 0; cc < 20; cc += 4) {
        __syncthreads();
        for (int e = tid; e < 4 * 18 * 66; e += 256) {
            int ch = e / (18 * 66);
            int r = (e / 66) % 18;
            int cl = e % 66;
            int gh = h0 + r - 1, gw = w0 + cl - 1;
            int c = cc + ch;
            float v = 0.f;
            if ((unsigned)gh < 1024u && (unsigned)gw < 1024u) {
                const float* src = (c < 16) ? (x + (((size_t)(b * 16 + c)) << 20))
                                            : g_a2[b * 4 + (c - 16)];
                v = src[gh * 1024 + gw];
            }
            sx[ch][r][cl] = v;
        }
        __syncthreads();
#pragma unroll
        for (int ch = 0; ch < 4; ch++) {
#pragma unroll
            for (int dy = 0; dy < 3; dy++) {
                float xr[6];
#pragma unroll
                for (int i = 0; i < 6; i++) xr[i] = sx[ch][ty + dy][tx * 4 + i];
#pragma unroll
                for (int dx = 0; dx < 3; dx++) {
                    int widx = (cc + ch) * 9 + dy * 3 + dx;
#pragma unroll
                    for (int o = 0; o < 16; o++) {
                        float wv_ = sw[o * 180 + widx];
#pragma unroll
                        for (int p = 0; p < 4; p++) acc[o][p] += wv_ * xr[p + dx];
                    }
                }
            }
        }
    }

    int gh = h0 + ty, gw = w0 + tx * 4;
#pragma unroll
    for (int o = 0; o < 16; o++) {
        float bb = bo[o];
        float4 v = make_float4(acc[o][0] + bb, acc[o][1] + bb, acc[o][2] + bb, acc[o][3] + bb);
        *(float4*)&out[(((size_t)(b * 16 + o)) << 20) + gh * 1024 + gw] = v;
    }
}

// ---------------- launch ----------------
extern "C" void kernel_launch(void* const* d_in, const int* in_sizes, int n_in,
                              void* d_out, int out_size) {
    const float* x       = (const float*)d_in[0];
    const float* prev_qk = (const float*)d_in[1];
    const float* mask    = (const float*)d_in[2];
    const float* wq_conv = (const float*)d_in[3];
    const float* bq_conv = (const float*)d_in[4];
    const float* wq_pw   = (const float*)d_in[5];
    const float* wk_conv = (const float*)d_in[6];
    const float* bk_conv = (const float*)d_in[7];
    const float* wk_pw   = (const float*)d_in[8];
    const float* wv_conv = (const float*)d_in[9];
    const float* bv_conv = (const float*)d_in[10];
    const float* wv_pw   = (const float*)d_in[11];
    const float* wo_pw   = (const float*)d_in[12];
    const float* wo_dw   = (const float*)d_in[13];
    const float* wo_conv = (const float*)d_in[14];
    const float* bo_conv = (const float*)d_in[15];

    float* outp = (float*)d_out;                       // (2,16,1024,1024)
    float* qk_out = outp + (size_t)NB * NC * NF * NW;  // (2,4,8,1024,1024)

    rope_init_kernel<<<64, 1024>>>();
    conv_qkv_kernel<<<dim3(NB, 64, 16), dim3(16, 16)>>>(x, wq_conv, bq_conv,
                                                        wk_conv, bk_conv, wv_conv, bv_conv);
    gemm_pw_t<<<dim3(8, 8, 8), 256>>>(wq_pw, 0, 1);
    gemm_pw_t<<<dim3(8, 8, 8), 256>>>(wk_pw, 1, 1);
    gemm_pw_t<<<dim3(8, 8, 8), 256>>>(wv_pw, 2, 0);
    gemm_qk_t<<<dim3(8, 8, 64), 256>>>(prev_qk, mask, qk_out);
    gemm_pv_t<<<dim3(8, 64), 256>>>(qk_out);
    dw_kernel<<<2048, 256>>>(wo_dw);
    gemm_wo_t<<<dim3(8, 8, 8), 256>>>(wo_pw);
    conv_out_kernel<<<dim3(NB, 64, 16), dim3(16, 16)>>>(x, wo_conv, bo_conv, outp);
}

// round 6
// speedup vs baseline: 1.1128x; 1.0341x over previous
#include <cuda_runtime.h>
#include <math.h>

// Problem dims
#define NB 2
#define NC 16
#define NAM 4
#define NHEADS 8
#define NF 1024
#define NW 1024
#define NHD 128

#define STR_K 136   // k-major smem stride (words)
#define STR_M 36    // m-major smem stride (words); (36*L)%32 tiles banks -> LDSM conflict-free
#define SLAB_K (32 * STR_K)    // 4352 words (32k x 128mn)
#define SLAB_M (128 * STR_M)   // 4608 words (128mn x 32k)

// ---------------- scratch (device globals; no runtime allocation) ----------------
__device__ float g_y[3][8][NF * NW];     // conv outputs for q,k,v
__device__ float g_t[3][8][NW * NF];     // qT,kT,vT
__device__ float g_a[8][NW * NF];        // attention out
__device__ float g_ao[8][NW * NF];       // after dw channel mix
__device__ float g_a2[8][NF * NW];       // after wo_pw
__device__ float g_p[(size_t)64 * 1024 * 1024];  // unnormalized exp(S)
__device__ float g_psum[64 * 1024 * 16]; // per-row exp partial sums
__device__ float g_cos[NW * (NHD / 2)];
__device__ float g_sin[NW * (NHD / 2)];

// ---------------- helpers ----------------
__device__ __forceinline__ unsigned sptr(const void* p) {
    return (unsigned)__cvta_generic_to_shared(p);
}
__device__ __forceinline__ void cpasync16(const void* dst_smem, const void* src_gmem) {
    asm volatile("cp.async.cg.shared.global [%0], [%1], 16;" ::"r"(sptr(dst_smem)),
                 "l"(src_gmem));
}
#define CP_COMMIT asm volatile("cp.async.commit_group;")
#define CP_WAIT0 asm volatile("cp.async.wait_group 0;")

__device__ __forceinline__ void ldsm_x4(unsigned r[4], const void* p) {
    asm volatile("ldmatrix.sync.aligned.m8n8.x4.shared.b16 {%0,%1,%2,%3}, [%4];"
                 : "=r"(r[0]), "=r"(r[1]), "=r"(r[2]), "=r"(r[3])
                 : "r"(sptr(p)));
}

__device__ __forceinline__ void mma_tf32(float* c, unsigned a0, unsigned a1, unsigned a2,
                                         unsigned a3, unsigned b0, unsigned b1) {
    asm volatile(
        "mma.sync.aligned.m16n8k8.row.col.f32.tf32.tf32.f32 "
        "{%0,%1,%2,%3}, {%4,%5,%6,%7}, {%8,%9}, {%0,%1,%2,%3};"
        : "+f"(c[0]), "+f"(c[1]), "+f"(c[2]), "+f"(c[3])
        : "r"(a0), "r"(a1), "r"(a2), "r"(a3), "r"(b0), "r"(b1));
}

// ---- fragment compute over a 16-k window at word-offset ko; 128x128 C, 8 warps 4(M)x2(N) ----
// A m-major LDSM + B m-major LDSM
__device__ __forceinline__ void fc_mm(const float* As, const float* Bs, int ko,
                                      float (&acc)[2][8][4], int lane, int warpM, int warpN) {
    const int la = lane & 15, ha = (lane >> 4) * 4;
    const int lb = lane & 7, hb = (lane >> 3) * 4;
    unsigned a[2][2][4];
#pragma unroll
    for (int mt = 0; mt < 2; mt++)
#pragma unroll
        for (int kk = 0; kk < 2; kk++)
            ldsm_x4(a[mt][kk], &As[(warpM * 32 + mt * 16 + la) * STR_M + ko + kk * 8 + ha]);
#pragma unroll
    for (int nh = 0; nh < 2; nh++) {
        unsigned b[4][4];
#pragma unroll
        for (int j = 0; j < 4; j++)
            ldsm_x4(b[j], &Bs[(warpN * 64 + nh * 32 + j * 8 + lb) * STR_M + ko + hb]);
#pragma unroll
        for (int kk = 0; kk < 2; kk++)
#pragma unroll
            for (int mt = 0; mt < 2; mt++)
#pragma unroll
                for (int j = 0; j < 4; j++)
                    mma_tf32(acc[mt][nh * 4 + j], a[mt][kk][0], a[mt][kk][1], a[mt][kk][2],
                             a[mt][kk][3], b[j][kk * 2], b[j][kk * 2 + 1]);
    }
}

// A k-major scalar + B m-major LDSM  (pw); ko in k-rows for A, words for B
__device__ __forceinline__ void fc_km(const float* As, const float* Bs, int ko,
                                      float (&acc)[2][8][4], int lane, int warpM, int warpN) {
    const int gid = lane >> 2, tig = lane & 3;
    const int lb = lane & 7, hb = (lane >> 3) * 4;
    unsigned a[2][2][4];
#pragma unroll
    for (int kk = 0; kk < 2; kk++) {
        const int k = ko + kk * 8;
#pragma unroll
        for (int mt = 0; mt < 2; mt++) {
            int rb = warpM * 32 + mt * 16 + gid;
            a[mt][kk][0] = __float_as_uint(As[(k + tig) * STR_K + rb]);
            a[mt][kk][1] = __float_as_uint(As[(k + tig) * STR_K + rb + 8]);
            a[mt][kk][2] = __float_as_uint(As[(k + 4 + tig) * STR_K + rb]);
            a[mt][kk][3] = __float_as_uint(As[(k + 4 + tig) * STR_K + rb + 8]);
        }
    }
#pragma unroll
    for (int nh = 0; nh < 2; nh++) {
        unsigned b[4][4];
#pragma unroll
        for (int j = 0; j < 4; j++)
            ldsm_x4(b[j], &Bs[(warpN * 64 + nh * 32 + j * 8 + lb) * STR_M + ko + hb]);
#pragma unroll
        for (int kk = 0; kk < 2; kk++)
#pragma unroll
            for (int mt = 0; mt < 2; mt++)
#pragma unroll
                for (int j = 0; j < 4; j++)
                    mma_tf32(acc[mt][nh * 4 + j], a[mt][kk][0], a[mt][kk][1], a[mt][kk][2],
                             a[mt][kk][3], b[j][kk * 2], b[j][kk * 2 + 1]);
    }
}

// A m-major LDSM + B k-major scalar  (pv)
__device__ __forceinline__ void fc_mk(const float* As, const float* Bs, int ko,
                                      float (&acc)[2][8][4], int lane, int warpM, int warpN) {
    const int la = lane & 15, ha = (lane >> 4) * 4;
    const int gid = lane >> 2, tig = lane & 3;
    unsigned a[2][2][4];
#pragma unroll
    for (int mt = 0; mt < 2; mt++)
#pragma unroll
        for (int kk = 0; kk < 2; kk++)
            ldsm_x4(a[mt][kk], &As[(warpM * 32 + mt * 16 + la) * STR_M + ko + kk * 8 + ha]);
#pragma unroll
    for (int kk = 0; kk < 2; kk++) {
        const int k = ko + kk * 8;
        unsigned bf[8][2];
#pragma unroll
        for (int nt = 0; nt < 8; nt++) {
            int cb = warpN * 64 + nt * 8 + gid;
            bf[nt][0] = __float_as_uint(Bs[(k + tig) * STR_K + cb]);
            bf[nt][1] = __float_as_uint(Bs[(k + 4 + tig) * STR_K + cb]);
        }
#pragma unroll
        for (int mt = 0; mt < 2; mt++)
#pragma unroll
            for (int nt = 0; nt < 8; nt++)
                mma_tf32(acc[mt][nt], a[mt][kk][0], a[mt][kk][1], a[mt][kk][2], a[mt][kk][3],
                         bf[nt][0], bf[nt][1]);
    }
}

// copy one 32(k) x 128(mn) k-major slab
__device__ __forceinline__ void copy_kmaj(float* buf, const float* src, int tid) {
#pragma unroll
    for (int i = 0; i < 4; i++) {
        int idx = tid + i * 256;
        int row = idx >> 5, c = (idx & 31) * 4;
        cpasync16(&buf[row * STR_K + c], &src[(size_t)row * 1024 + c]);
    }
}
// copy one 128(mn) x 32(k) m-major slab
__device__ __forceinline__ void copy_mmaj(float* buf, const float* src, int tid) {
#pragma unroll
    for (int i = 0; i < 4; i++) {
        int idx = tid + i * 256;
        int row = idx >> 3, c = (idx & 7) * 4;
        cpasync16(&buf[row * STR_M + c], &src[(size_t)row * 1024 + c]);
    }
}

// ---------------- RoPE table init ----------------
__global__ void rope_init_kernel() {
    int idx = blockIdx.x * blockDim.x + threadIdx.x;
    if (idx >= NW * 64) return;
    int w = idx >> 6, j = idx & 63;
    double inv = exp(-((double)(2 * j) / (double)NHD) * log(10000.0));
    double ang = (double)w * inv;
    g_cos[idx] = (float)cos(ang);
    g_sin[idx] = (float)sin(ang);
}

// ---------------- conv 3x3 (16 -> 4) producing q,k,v conv outputs in one pass ----------------
__global__ __launch_bounds__(256) void conv_qkv_kernel(
    const float* __restrict__ x,
    const float* __restrict__ wq, const float* __restrict__ bq,
    const float* __restrict__ wk, const float* __restrict__ bk,
    const float* __restrict__ wv, const float* __restrict__ bv) {
    __shared__ float sx[4][18][68];
    __shared__ float sw[3 * 4 * 16 * 9];
    const int b = blockIdx.x;
    const int h0 = blockIdx.y * 16;
    const int w0 = blockIdx.z * 64;
    const int tx = threadIdx.x, ty = threadIdx.y;
    const int tid = ty * 16 + tx;

    for (int i = tid; i < 576; i += 256) {
        sw[i] = wq[i];
        sw[576 + i] = wk[i];
        sw[1152 + i] = wv[i];
    }

    float acc[12][4];
#pragma unroll
    for (int o = 0; o < 12; o++)
#pragma unroll
        for (int p = 0; p < 4; p++) acc[o][p] = 0.f;

    for (int cc = 0; cc < 16; cc += 4) {
        __syncthreads();
        for (int e = tid; e < 4 * 18 * 66; e += 256) {
            int ch = e / (18 * 66);
            int r = (e / 66) % 18;
            int cl = e % 66;
            int gh = h0 + r - 1, gw = w0 + cl - 1;
            float v = 0.f;
            if ((unsigned)gh < 1024u && (unsigned)gw < 1024u)
                v = x[(((size_t)(b * 16 + cc + ch)) << 20) + gh * 1024 + gw];
            sx[ch][r][cl] = v;
        }
        __syncthreads();
#pragma unroll
        for (int ch = 0; ch < 4; ch++) {
#pragma unroll
            for (int dy = 0; dy < 3; dy++) {
                float xr[6];
#pragma unroll
                for (int i = 0; i < 6; i++) xr[i] = sx[ch][ty + dy][tx * 4 + i];
#pragma unroll
                for (int dx = 0; dx < 3; dx++) {
                    int widx = (cc + ch) * 9 + dy * 3 + dx;
#pragma unroll
                    for (int o = 0; o < 12; o++) {
                        float wv_ = sw[(o >> 2) * 576 + (o & 3) * 144 + widx];
#pragma unroll
                        for (int p = 0; p < 4; p++) acc[o][p] += wv_ * xr[p + dx];
                    }
                }
            }
        }
    }

    int gh = h0 + ty, gw = w0 + tx * 4;
#pragma unroll
    for (int t = 0; t < 3; t++) {
        const float* bias = (t == 0) ? bq : (t == 1) ? bk : bv;
#pragma unroll
        for (int m = 0; m < 4; m++) {
            float bb = bias[m];
            float4 v = make_float4(acc[t * 4 + m][0] + bb, acc[t * 4 + m][1] + bb,
                                   acc[t * 4 + m][2] + bb, acc[t * 4 + m][3] + bb);
            *(float4*)&g_y[t][b * 4 + m][gh * 1024 + gw] = v;
        }
    }
}

// ---------------- pw linear: OutT[w,f] = sum_h Wt[f,h] * Y[h,w]; optional RoPE ----------------
__global__ __launch_bounds__(256, 2) void gemm_pw_t(const float* __restrict__ Wpw, int t,
                                                    int do_rope) {
    const int m0 = blockIdx.x * 128;  // w
    const int n0 = blockIdx.y * 128;  // f
    const int b4 = blockIdx.z;
    const int am = b4 & 3;
    const float* Y = g_y[t][b4];
    const float* Wt = Wpw + ((size_t)am << 20);
    float* Out = g_t[t][b4];

    extern __shared__ __align__(16) float sh[];
    float* A0 = sh;                 // 2 x SLAB_K (k-major)
    float* B0 = sh + 2 * SLAB_K;    // 2 x SLAB_M (n-major)
    const int tid = threadIdx.x;
    const int lane = tid & 31, warp = tid >> 5, warpM = warp & 3, warpN = warp >> 2;
    const int gid = lane >> 2, tig = lane & 3;

    float acc[2][8][4] = {};

    copy_kmaj(A0, Y + m0, tid);
    copy_mmaj(B0, Wt + (size_t)n0 * 1024, tid);
    CP_COMMIT;

    for (int it = 0; it < 32; it++) {
        const int cur = it & 1;
        CP_WAIT0;
        __syncthreads();
        if (it + 1 < 32) {
            copy_kmaj(A0 + (cur ^ 1) * SLAB_K, Y + (size_t)(it + 1) * 32 * 1024 + m0, tid);
            copy_mmaj(B0 + (cur ^ 1) * SLAB_M, Wt + (size_t)n0 * 1024 + (it + 1) * 32, tid);
            CP_COMMIT;
        }
        fc_km(A0 + cur * SLAB_K, B0 + cur * SLAB_M, 0, acc, lane, warpM, warpN);
        fc_km(A0 + cur * SLAB_K, B0 + cur * SLAB_M, 16, acc, lane, warpM, warpN);
    }

#pragma unroll
    for (int mt = 0; mt < 2; mt++)
#pragma unroll
        for (int half = 0; half < 2; half++) {
            int w = m0 + warpM * 32 + mt * 16 + gid + half * 8;
#pragma unroll
            for (int nt = 0; nt < 8; nt++) {
                int f = n0 + warpN * 64 + nt * 8 + 2 * tig;
                float v0 = acc[mt][nt][half * 2 + 0];
                float v1 = acc[mt][nt][half * 2 + 1];
                if (do_rope) {
                    int j0 = (f >> 1) & 63;
                    float c = g_cos[w * 64 + j0], s = g_sin[w * 64 + j0];
                    float e = v0 * c - v1 * s, o = v1 * c + v0 * s;
                    v0 = e;
                    v1 = o;
                }
                *(float2*)&Out[(size_t)w * 1024 + f] = make_float2(v0, v1);
            }
        }
}

// ---------------- S = q k^T / 32 + prev_qk + mask; writes S, exp(S), partial row sums -------
__global__ __launch_bounds__(256, 2) void gemm_qk_t(const float* __restrict__ prev_qk,
                                                    const float* __restrict__ mask,
                                                    float* __restrict__ qk_out) {
    const int m0 = blockIdx.x * 128;
    const int n0 = blockIdx.y * 128;
    const int bh = blockIdx.z;
    const int b4 = bh >> 3, head = bh & 7;
    const float* Qb = g_t[0][b4] + head * 128;
    const float* Kb = g_t[1][b4] + head * 128;

    extern __shared__ __align__(16) float sh[];
    float* A0 = sh;               // 2 x SLAB_M
    float* B0 = sh + 2 * SLAB_M;  // 2 x SLAB_M
    const int tid = threadIdx.x;
    const int lane = tid & 31, warp = tid >> 5, warpM = warp & 3, warpN = warp >> 2;
    const int gid = lane >> 2, tig = lane & 3;

    float acc[2][8][4] = {};

    copy_mmaj(A0, Qb + (size_t)m0 * 1024, tid);
    copy_mmaj(B0, Kb + (size_t)n0 * 1024, tid);
    CP_COMMIT;

    for (int it = 0; it < 4; it++) {
        const int cur = it & 1;
        CP_WAIT0;
        __syncthreads();
        if (it + 1 < 4) {
            copy_mmaj(A0 + (cur ^ 1) * SLAB_M, Qb + (size_t)m0 * 1024 + (it + 1) * 32, tid);
            copy_mmaj(B0 + (cur ^ 1) * SLAB_M, Kb + (size_t)n0 * 1024 + (it + 1) * 32, tid);
            CP_COMMIT;
        }
        fc_mm(A0 + cur * SLAB_M, B0 + cur * SLAB_M, 0, acc, lane, warpM, warpN);
        fc_mm(A0 + cur * SLAB_M, B0 + cur * SLAB_M, 16, acc, lane, warpM, warpN);
    }

    const float* prevb = prev_qk + ((size_t)bh << 20);
    float* outb = qk_out + ((size_t)bh << 20);
    float* pb = g_p + ((size_t)bh << 20);
#pragma unroll
    for (int mt = 0; mt < 2; mt++)
#pragma unroll
        for (int half = 0; half < 2; half++) {
            int mi = m0 + warpM * 32 + mt * 16 + gid + half * 8;
            float rowsum = 0.f;
#pragma unroll
            for (int nt = 0; nt < 8; nt++) {
                int n = n0 + warpN * 64 + nt * 8 + 2 * tig;
                float2 pv = *(const float2*)&prevb[(size_t)mi * 1024 + n];
                float2 mk = *(const float2*)&mask[(size_t)mi * 1024 + n];
                float2 r;
                r.x = acc[mt][nt][half * 2 + 0] * 0.03125f + pv.x + mk.x;
                r.y = acc[mt][nt][half * 2 + 1] * 0.03125f + pv.y + mk.y;
                *(float2*)&outb[(size_t)mi * 1024 + n] = r;
                float2 e = make_float2(__expf(r.x), __expf(r.y));
                *(float2*)&pb[(size_t)mi * 1024 + n] = e;
                rowsum += e.x + e.y;
            }
            rowsum += __shfl_xor_sync(0xffffffffu, rowsum, 1);
            rowsum += __shfl_xor_sync(0xffffffffu, rowsum, 2);
            if (tig == 0)
                g_psum[((size_t)bh * 1024 + mi) * 16 + blockIdx.y * 2 + warpN] = rowsum;
        }
}

// ---------------- A = P @ V with per-row 1/sum folded into epilogue ----------------
__global__ __launch_bounds__(256, 2) void gemm_pv_t() {
    const int m0 = blockIdx.x * 128;
    const int bh = blockIdx.y;
    const int b4 = bh >> 3, head = bh & 7;
    const float* Pb = g_p + ((size_t)bh << 20);
    const float* Vb = g_t[2][b4] + head * 128;
    float* Ab = g_a[b4];

    extern __shared__ __align__(16) float sh[];
    float* A0 = sh;                // 2 x SLAB_M (m-major P)
    float* B0 = sh + 2 * SLAB_M;   // 2 x SLAB_K (k-major V)
    float* srinv = sh + 2 * SLAB_M + 2 * SLAB_K;  // 128
    const int tid = threadIdx.x;
    const int lane = tid & 31, warp = tid >> 5, warpM = warp & 3, warpN = warp >> 2;
    const int gid = lane >> 2, tig = lane & 3;

    // per-row normalizer from the 16 deterministic partials
    {
        int row = tid >> 1, hh = tid & 1;
        const float* ps = &g_psum[((size_t)bh * 1024 + m0 + row) * 16 + hh * 8];
        float s = 0.f;
#pragma unroll
        for (int i = 0; i < 8; i++) s += ps[i];
        s += __shfl_xor_sync(0xffffffffu, s, 1);
        if (hh == 0) srinv[row] = 1.0f / s;
    }

    float acc[2][8][4] = {};

    copy_mmaj(A0, Pb + (size_t)m0 * 1024, tid);
    copy_kmaj(B0, Vb, tid);
    CP_COMMIT;

    for (int it = 0; it < 32; it++) {
        const int cur = it & 1;
        CP_WAIT0;
        __syncthreads();
        if (it + 1 < 32) {
            copy_mmaj(A0 + (cur ^ 1) * SLAB_M, Pb + (size_t)m0 * 1024 + (it + 1) * 32, tid);
            copy_kmaj(B0 + (cur ^ 1) * SLAB_K, Vb + (size_t)(it + 1) * 32 * 1024, tid);
            CP_COMMIT;
        }
        fc_mk(A0 + cur * SLAB_M, B0 + cur * SLAB_K, 0, acc, lane, warpM, warpN);
        fc_mk(A0 + cur * SLAB_M, B0 + cur * SLAB_K, 16, acc, lane, warpM, warpN);
    }

#pragma unroll
    for (int mt = 0; mt < 2; mt++)
#pragma unroll
        for (int half = 0; half < 2; half++) {
            int ml = warpM * 32 + mt * 16 + gid + half * 8;
            int mi = m0 + ml;
            float rv = srinv[ml];
#pragma unroll
            for (int nt = 0; nt < 8; nt++) {
                int n = warpN * 64 + nt * 8 + 2 * tig;
                float2 r = make_float2(acc[mt][nt][half * 2 + 0] * rv,
                                       acc[mt][nt][half * 2 + 1] * rv);
                *(float2*)&Ab[(size_t)mi * 1024 + head * 128 + n] = r;
            }
        }
}

// ---------------- 4x4 depthwise channel mix ----------------
__global__ __launch_bounds__(256) void dw_kernel(const float* __restrict__ dw) {
    int idx = blockIdx.x * 256 + threadIdx.x;
    int b = idx >> 18;
    size_t off = ((size_t)(idx & 262143)) << 2;
    float4 a[4];
#pragma unroll
    for (int c = 0; c < 4; c++) a[c] = *(const float4*)&g_a[b * 4 + c][off];
#pragma unroll
    for (int o = 0; o < 4; o++) {
        float w0 = dw[o * 4 + 0], w1 = dw[o * 4 + 1], w2 = dw[o * 4 + 2], w3 = dw[o * 4 + 3];
        float4 r;
        r.x = w0 * a[0].x + w1 * a[1].x + w2 * a[2].x + w3 * a[3].x;
        r.y = w0 * a[0].y + w1 * a[1].y + w2 * a[2].y + w3 * a[3].y;
        r.z = w0 * a[0].z + w1 * a[1].z + w2 * a[2].z + w3 * a[3].z;
        r.w = w0 * a[0].w + w1 * a[1].w + w2 * a[2].w + w3 * a[3].w;
        *(float4*)&g_ao[b * 4 + o][off] = r;
    }
}

// ---------------- wo_pw: Out[f,w] = sum_h Wt[f,h] * AoT[w,h] ----------------
__global__ __launch_bounds__(256, 2) void gemm_wo_t(const float* __restrict__ Wopw) {
    const int m0 = blockIdx.x * 128;  // f
    const int n0 = blockIdx.y * 128;  // w
    const int b4 = blockIdx.z;
    const int am = b4 & 3;
    const float* Wt = Wopw + ((size_t)am << 20);
    const float* Ao = g_ao[b4];
    float* Out = g_a2[b4];

    extern __shared__ __align__(16) float sh[];
    float* A0 = sh;
    float* B0 = sh + 2 * SLAB_M;
    const int tid = threadIdx.x;
    const int lane = tid & 31, warp = tid >> 5, warpM = warp & 3, warpN = warp >> 2;
    const int gid = lane >> 2, tig = lane & 3;

    float acc[2][8][4] = {};

    copy_mmaj(A0, Wt + (size_t)m0 * 1024, tid);
    copy_mmaj(B0, Ao + (size_t)n0 * 1024, tid);
    CP_COMMIT;

    for (int it = 0; it < 32; it++) {
        const int cur = it & 1;
        CP_WAIT0;
        __syncthreads();
        if (it + 1 < 32) {
            copy_mmaj(A0 + (cur ^ 1) * SLAB_M, Wt + (size_t)m0 * 1024 + (it + 1) * 32, tid);
            copy_mmaj(B0 + (cur ^ 1) * SLAB_M, Ao + (size_t)n0 * 1024 + (it + 1) * 32, tid);
            CP_COMMIT;
        }
        fc_mm(A0 + cur * SLAB_M, B0 + cur * SLAB_M, 0, acc, lane, warpM, warpN);
        fc_mm(A0 + cur * SLAB_M, B0 + cur * SLAB_M, 16, acc, lane, warpM, warpN);
    }

#pragma unroll
    for (int mt = 0; mt < 2; mt++)
#pragma unroll
        for (int half = 0; half < 2; half++) {
            int mi = m0 + warpM * 32 + mt * 16 + gid + half * 8;
#pragma unroll
            for (int nt = 0; nt < 8; nt++) {
                int n = n0 + warpN * 64 + nt * 8 + 2 * tig;
                float2 r = make_float2(acc[mt][nt][half * 2 + 0], acc[mt][nt][half * 2 + 1]);
                *(float2*)&Out[(size_t)mi * 1024 + n] = r;
            }
        }
}

// ---------------- final conv 3x3 over concat(x[16], a2[4]) -> 16 channels ----------------
__global__ __launch_bounds__(256) void conv_out_kernel(const float* __restrict__ x,
                                                       const float* __restrict__ wo,
                                                       const float* __restrict__ bo,
                                                       float* __restrict__ out) {
    __shared__ float sx[4][18][68];
    __shared__ float sw[16 * 20 * 9];
    const int b = blockIdx.x;
    const int h0 = blockIdx.y * 16;
    const int w0 = blockIdx.z * 64;
    const int tx = threadIdx.x, ty = threadIdx.y;
    const int tid = ty * 16 + tx;

    for (int i = tid; i < 2880; i += 256) sw[i] = wo[i];

    float acc[16][4];
#pragma unroll
    for (int o = 0; o < 16; o++)
#pragma unroll
        for (int p = 0; p < 4; p++) acc[o][p] = 0.f;

    for (int cc = 0; cc < 20; cc += 4) {
        __syncthreads();
        for (int e = tid; e < 4 * 18 * 66; e += 256) {
            int ch = e / (18 * 66);
            int r = (e / 66) % 18;
            int cl = e % 66;
            int gh = h0 + r - 1, gw = w0 + cl - 1;
            int c = cc + ch;
            float v = 0.f;
            if ((unsigned)gh < 1024u && (unsigned)gw < 1024u) {
                const float* src = (c < 16) ? (x + (((size_t)(b * 16 + c)) << 20))
                                            : g_a2[b * 4 + (c - 16)];
                v = src[gh * 1024 + gw];
            }
            sx[ch][r][cl] = v;
        }
        __syncthreads();
#pragma unroll
        for (int ch = 0; ch < 4; ch++) {
#pragma unroll
            for (int dy = 0; dy < 3; dy++) {
                float xr[6];
#pragma unroll
                for (int i = 0; i < 6; i++) xr[i] = sx[ch][ty + dy][tx * 4 + i];
#pragma unroll
                for (int dx = 0; dx < 3; dx++) {
                    int widx = (cc + ch) * 9 + dy * 3 + dx;
#pragma unroll
                    for (int o = 0; o < 16; o++) {
                        float wv_ = sw[o * 180 + widx];
#pragma unroll
                        for (int p = 0; p < 4; p++) acc[o][p] += wv_ * xr[p + dx];
                    }
                }
            }
        }
    }

    int gh = h0 + ty, gw = w0 + tx * 4;
#pragma unroll
    for (int o = 0; o < 16; o++) {
        float bb = bo[o];
        float4 v = make_float4(acc[o][0] + bb, acc[o][1] + bb, acc[o][2] + bb, acc[o][3] + bb);
        *(float4*)&out[(((size_t)(b * 16 + o)) << 20) + gh * 1024 + gw] = v;
    }
}

// ---------------- launch ----------------
extern "C" void kernel_launch(void* const* d_in, const int* in_sizes, int n_in,
                              void* d_out, int out_size) {
    const float* x       = (const float*)d_in[0];
    const float* prev_qk = (const float*)d_in[1];
    const float* mask    = (const float*)d_in[2];
    const float* wq_conv = (const float*)d_in[3];
    const float* bq_conv = (const float*)d_in[4];
    const float* wq_pw   = (const float*)d_in[5];
    const float* wk_conv = (const float*)d_in[6];
    const float* bk_conv = (const float*)d_in[7];
    const float* wk_pw   = (const float*)d_in[8];
    const float* wv_conv = (const float*)d_in[9];
    const float* bv_conv = (const float*)d_in[10];
    const float* wv_pw   = (const float*)d_in[11];
    const float* wo_pw   = (const float*)d_in[12];
    const float* wo_dw   = (const float*)d_in[13];
    const float* wo_conv = (const float*)d_in[14];
    const float* bo_conv = (const float*)d_in[15];

    float* outp = (float*)d_out;                       // (2,16,1024,1024)
    float* qk_out = outp + (size_t)NB * NC * NF * NW;  // (2,4,8,1024,1024)

    const int PW_SM = (2 * SLAB_K + 2 * SLAB_M) * 4;        // 71680
    const int MM_SM = (4 * SLAB_M) * 4;                     // 73728
    const int PV_SM = (2 * SLAB_M + 2 * SLAB_K) * 4 + 512;  // 72192

    cudaFuncSetAttribute(gemm_pw_t, cudaFuncAttributeMaxDynamicSharedMemorySize, PW_SM);
    cudaFuncSetAttribute(gemm_qk_t, cudaFuncAttributeMaxDynamicSharedMemorySize, MM_SM);
    cudaFuncSetAttribute(gemm_wo_t, cudaFuncAttributeMaxDynamicSharedMemorySize, MM_SM);
    cudaFuncSetAttribute(gemm_pv_t, cudaFuncAttributeMaxDynamicSharedMemorySize, PV_SM);

    rope_init_kernel<<<64, 1024>>>();
    conv_qkv_kernel<<<dim3(NB, 64, 16), dim3(16, 16)>>>(x, wq_conv, bq_conv,
                                                        wk_conv, bk_conv, wv_conv, bv_conv);
    gemm_pw_t<<<dim3(8, 8, 8), 256, PW_SM>>>(wq_pw, 0, 1);
    gemm_pw_t<<<dim3(8, 8, 8), 256, PW_SM>>>(wk_pw, 1, 1);
    gemm_pw_t<<<dim3(8, 8, 8), 256, PW_SM>>>(wv_pw, 2, 0);
    gemm_qk_t<<<dim3(8, 8, 64), 256, MM_SM>>>(prev_qk, mask, qk_out);
    gemm_pv_t<<<dim3(8, 64), 256, PV_SM>>>();
    dw_kernel<<<2048, 256>>>(wo_dw);
    gemm_wo_t<<<dim3(8, 8, 8), 256, MM_SM>>>(wo_pw);
    conv_out_kernel<<<dim3(NB, 64, 16), dim3(16, 16)>>>(x, wo_conv, bo_conv, outp);
}

// round 8
// speedup vs baseline: 1.1480x; 1.0316x over previous
#include <cuda_runtime.h>
#include <math.h>

// Problem dims
#define NB 2
#define NC 16
#define NAM 4
#define NHEADS 8
#define NF 1024
#define NW 1024
#define NHD 128

// Tiled-slab layout: slab = 128 rows x 32 k, rows padded to 36 words -> 18432B contiguous
#define TSTR 36
#define TSLAB 4608
#define TSLAB_B 18432u
#define TMB 147456
#define TMAT 1179648

// ---------------- scratch (device globals; no runtime allocation) ----------------
__device__ float g_yt[3][8][TMAT];      // conv outputs tiled: rows=w, k=h
__device__ float g_qkm[2][8][TMAT];     // q,k tiled: rows=w, k=f
__device__ float g_vt[8][TMAT];         // V^T tiled: rows=f, k=w
__device__ float g_wt[4][4][TMAT];      // repacked weights [q,k,v,o][am]: rows=f, k=h
__device__ float g_pt[(size_t)64 * TMAT];  // exp(S) tiled per bh
__device__ float g_aot[8][TMAT];        // after dw mix tiled: rows=w, k=h
__device__ float g_a[8][NW * NF];       // attention out plain [w][f]
__device__ float g_a2[8][NF * NW];      // after wo_pw plain [f][w]
__device__ float g_psum[64 * 1024 * 16];
__device__ float g_cos[NW * (NHD / 2)];
__device__ float g_sin[NW * (NHD / 2)];

// ---------------- helpers ----------------
__device__ __forceinline__ unsigned sptr(const void* p) {
    return (unsigned)__cvta_generic_to_shared(p);
}
__device__ __forceinline__ size_t tiled_off(int row, int k) {
    return (size_t)(row >> 7) * TMB + (size_t)(k >> 5) * TSLAB + (row & 127) * TSTR + (k & 31);
}

#define MBARRIER_INIT(addr, count) \
    asm volatile("mbarrier.init.shared.b64 [%0], %1;" ::"r"(addr), "r"(count) : "memory")

#define MBARRIER_WAIT_PARITY(addr, parity)                                              \
    do {                                                                                \
        unsigned _mb = (addr), _pa = (parity), _done;                                   \
        asm volatile(                                                                   \
            "{\n\t.reg .pred p;\n\t"                                                    \
            "mbarrier.try_wait.parity.acquire.cta.shared::cta.b64 p, [%1], %2;\n\t"     \
            "selp.b32 %0, 1, 0, p;\n\t}"                                                \
            : "=r"(_done) : "r"(_mb), "r"(_pa) : "memory");                             \
        if (!_done) {                                                                   \
            asm volatile(                                                               \
                "{\n\t.reg .pred P1;\n\t"                                               \
                "WL_%=:\n\t"                                                            \
                "mbarrier.try_wait.parity.acquire.cta.shared::cta.b64 P1, [%0], %1, 0x989680;\n\t" \
                "@P1 bra.uni WD_%=;\n\t"                                                \
                "bra.uni WL_%=;\n\t"                                                    \
                "WD_%=:\n\t}" ::"r"(_mb), "r"(_pa) : "memory");                         \
        }                                                                               \
    } while (0)

__device__ __forceinline__ void bulk_expect(unsigned mb, unsigned bytes) {
    asm volatile("mbarrier.arrive.expect_tx.shared.b64 _, [%0], %1;" ::"r"(mb), "r"(bytes)
                 : "memory");
}
__device__ __forceinline__ void bulk_cp(unsigned dst, const float* src, unsigned mb) {
    asm volatile(
        "cp.async.bulk.shared::cta.global.mbarrier::complete_tx::bytes [%0], [%1], %2, [%3];"
        ::"r"(dst), "l"(src), "r"(TSLAB_B), "r"(mb)
        : "memory");
}

__device__ __forceinline__ void ldsm_x4(unsigned r[4], const void* p) {
    asm volatile("ldmatrix.sync.aligned.m8n8.x4.shared.b16 {%0,%1,%2,%3}, [%4];"
                 : "=r"(r[0]), "=r"(r[1]), "=r"(r[2]), "=r"(r[3])
                 : "r"(sptr(p)));
}
__device__ __forceinline__ void mma_tf32(float* c, unsigned a0, unsigned a1, unsigned a2,
                                         unsigned a3, unsigned b0, unsigned b1) {
    asm volatile(
        "mma.sync.aligned.m16n8k8.row.col.f32.tf32.tf32.f32 "
        "{%0,%1,%2,%3}, {%4,%5,%6,%7}, {%8,%9}, {%0,%1,%2,%3};"
        : "+f"(c[0]), "+f"(c[1]), "+f"(c[2]), "+f"(c[3])
        : "r"(a0), "r"(a1), "r"(a2), "r"(a3), "r"(b0), "r"(b1));
}

// fragment compute over one 16-k window at word-offset ko; both operands m-major (TSTR)
__device__ __forceinline__ void fc_mm(const float* As, const float* Bs, int ko,
                                      float (&acc)[2][8][4], int lane, int warpM, int warpN) {
    const int la = lane & 15, ha = (lane >> 4) * 4;
    const int lb = lane & 7, hb = (lane >> 3) * 4;
    unsigned a[2][2][4];
#pragma unroll
    for (int mt = 0; mt < 2; mt++)
#pragma unroll
        for (int kk = 0; kk < 2; kk++)
            ldsm_x4(a[mt][kk], &As[(warpM * 32 + mt * 16 + la) * TSTR + ko + kk * 8 + ha]);
#pragma unroll
    for (int nh = 0; nh < 2; nh++) {
        unsigned b[4][4];
#pragma unroll
        for (int j = 0; j < 4; j++)
            ldsm_x4(b[j], &Bs[(warpN * 64 + nh * 32 + j * 8 + lb) * TSTR + ko + hb]);
#pragma unroll
        for (int kk = 0; kk < 2; kk++)
#pragma unroll
            for (int mt = 0; mt < 2; mt++)
#pragma unroll
                for (int j = 0; j < 4; j++)
                    mma_tf32(acc[mt][nh * 4 + j], a[mt][kk][0], a[mt][kk][1], a[mt][kk][2],
                             a[mt][kk][3], b[j][kk * 2], b[j][kk * 2 + 1]);
    }
}

// bulk-copy double-buffered mainloop over NIT contiguous 18KB slabs per operand
__device__ __forceinline__ void bulk_mainloop(const float* A, const float* B, int NIT,
                                              float* sh, unsigned mb0, float (&acc)[2][8][4],
                                              int tid, int lane, int warpM, int warpN) {
    const unsigned shu = sptr(sh);
    if (tid == 0) {
        bulk_expect(mb0, 2 * TSLAB_B);
        bulk_cp(shu, A, mb0);
        bulk_cp(shu + 2 * TSLAB_B, B, mb0);
        bulk_expect(mb0 + 8, 2 * TSLAB_B);
        bulk_cp(shu + TSLAB_B, A + TSLAB, mb0 + 8);
        bulk_cp(shu + 3 * TSLAB_B, B + TSLAB, mb0 + 8);
    }
    int ph0 = 0, ph1 = 0;
    for (int it = 0; it < NIT; it++) {
        const int s = it & 1;
        if (s == 0) {
            MBARRIER_WAIT_PARITY(mb0, ph0);
            ph0 ^= 1;
        } else {
            MBARRIER_WAIT_PARITY(mb0 + 8, ph1);
            ph1 ^= 1;
        }
        const float* As = sh + s * TSLAB;
        const float* Bs = sh + 2 * TSLAB + s * TSLAB;
        fc_mm(As, Bs, 0, acc, lane, warpM, warpN);
        fc_mm(As, Bs, 16, acc, lane, warpM, warpN);
        __syncthreads();
        if (it + 2 < NIT && tid == 0) {
            const unsigned mb = mb0 + s * 8;
            bulk_expect(mb, 2 * TSLAB_B);
            bulk_cp(shu + s * TSLAB_B, A + (size_t)(it + 2) * TSLAB, mb);
            bulk_cp(shu + 2 * TSLAB_B + s * TSLAB_B, B + (size_t)(it + 2) * TSLAB, mb);
        }
    }
}

#define GEMM_PROLOG                                                          \
    extern __shared__ __align__(16) float sh[];                              \
    __shared__ __align__(8) unsigned long long s_mb[2];                      \
    const int tid = threadIdx.x;                                             \
    const int lane = tid & 31, warp = tid >> 5, warpM = warp & 3,            \
              warpN = warp >> 2;                                             \
    const int gid = lane >> 2, tig = lane & 3;                               \
    if (tid == 0) {                                                          \
        MBARRIER_INIT(sptr(&s_mb[0]), 1);                                    \
        MBARRIER_INIT(sptr(&s_mb[1]), 1);                                    \
    }                                                                        \
    __syncthreads();                                                         \
    const unsigned mb0 = sptr(&s_mb[0]);                                     \
    float acc[2][8][4] = {};

// ---------------- weight repack: plain [am][f][h] -> g_wt[which] tiled ----------------
__global__ __launch_bounds__(256) void repack_kernel(const float* __restrict__ src, int which) {
    const float* s = src + ((size_t)blockIdx.z << 20) + ((size_t)blockIdx.x * 128) * 1024 +
                     blockIdx.y * 32;
    float* d = &g_wt[which][blockIdx.z][(size_t)blockIdx.x * TMB + (size_t)blockIdx.y * TSLAB];
    const int warp = threadIdx.x >> 5, lane = threadIdx.x & 31;
#pragma unroll
    for (int i = 0; i < 16; i++) {
        int r = warp * 16 + i;
        d[r * TSTR + lane] = s[(size_t)r * 1024 + lane];
    }
}

// ---------------- RoPE table init ----------------
__global__ void rope_init_kernel() {
    int idx = blockIdx.x * blockDim.x + threadIdx.x;
    if (idx >= NW * 64) return;
    int w = idx >> 6, j = idx & 63;
    double inv = exp(-((double)(2 * j) / (double)NHD) * log(10000.0));
    double ang = (double)w * inv;
    g_cos[idx] = (float)cos(ang);
    g_sin[idx] = (float)sin(ang);
}

// ---------------- conv 3x3 (16 -> 4) writing tiled-transposed Yt (rows=w, k=h) ------------
__global__ __launch_bounds__(256) void conv_qkv_kernel(
    const float* __restrict__ x,
    const float* __restrict__ wq, const float* __restrict__ bq,
    const float* __restrict__ wk, const float* __restrict__ bk,
    const float* __restrict__ wv, const float* __restrict__ bv) {
    __shared__ float sx[4][18][68];
    __shared__ float sw[3 * 4 * 16 * 9];
    __shared__ float st[16][68];
    const int b = blockIdx.x;
    const int h0 = blockIdx.y * 16;
    const int w0 = blockIdx.z * 64;
    const int tx = threadIdx.x, ty = threadIdx.y;
    const int tid = ty * 16 + tx;

    for (int i = tid; i < 576; i += 256) {
        sw[i] = wq[i];
        sw[576 + i] = wk[i];
        sw[1152 + i] = wv[i];
    }

    float acc[12][4];
#pragma unroll
    for (int o = 0; o < 12; o++)
#pragma unroll
        for (int p = 0; p < 4; p++) acc[o][p] = 0.f;

    for (int cc = 0; cc < 16; cc += 4) {
        __syncthreads();
        for (int e = tid; e < 4 * 18 * 66; e += 256) {
            int ch = e / (18 * 66);
            int r = (e / 66) % 18;
            int cl = e % 66;
            int gh = h0 + r - 1, gw = w0 + cl - 1;
            float v = 0.f;
            if ((unsigned)gh < 1024u && (unsigned)gw < 1024u)
                v = x[(((size_t)(b * 16 + cc + ch)) << 20) + gh * 1024 + gw];
            sx[ch][r][cl] = v;
        }
        __syncthreads();
#pragma unroll
        for (int ch = 0; ch < 4; ch++) {
#pragma unroll
            for (int dy = 0; dy < 3; dy++) {
                float xr[6];
#pragma unroll
                for (int i = 0; i < 6; i++) xr[i] = sx[ch][ty + dy][tx * 4 + i];
#pragma unroll
                for (int dx = 0; dx < 3; dx++) {
                    int widx = (cc + ch) * 9 + dy * 3 + dx;
#pragma unroll
                    for (int o = 0; o < 12; o++) {
                        float wv_ = sw[(o >> 2) * 576 + (o & 3) * 144 + widx];
#pragma unroll
                        for (int p = 0; p < 4; p++) acc[o][p] += wv_ * xr[p + dx];
                    }
                }
            }
        }
    }

    const int wloc = tid >> 2, q = tid & 3;
#pragma unroll
    for (int t = 0; t < 3; t++) {
        const float* bias = (t == 0) ? bq : (t == 1) ? bk : bv;
#pragma unroll
        for (int m = 0; m < 4; m++) {
            float bb = bias[m];
            __syncthreads();
#pragma unroll
            for (int p = 0; p < 4; p++) st[ty][tx * 4 + p] = acc[t * 4 + m][p] + bb;
            __syncthreads();
            float4 v = make_float4(st[q * 4 + 0][wloc], st[q * 4 + 1][wloc],
                                   st[q * 4 + 2][wloc], st[q * 4 + 3][wloc]);
            *(float4*)&g_yt[t][b * 4 + m][tiled_off(w0 + wloc, h0 + q * 4)] = v;
        }
    }
}

// ---------------- pw linear: q/k (+rope) -> tiled; v -> V^T tiled ----------------
__global__ __launch_bounds__(256, 2) void gemm_pw_t(int t, int do_rope) {
    const int m0 = blockIdx.x * 128;  // w
    const int n0 = blockIdx.y * 128;  // f
    const int b4 = blockIdx.z;
    const int am = b4 & 3;
    GEMM_PROLOG;

    const float* A = &g_yt[t][b4][(size_t)(m0 >> 7) * TMB];
    const float* B = &g_wt[t][am][(size_t)(n0 >> 7) * TMB];
    bulk_mainloop(A, B, 32, sh, mb0, acc, tid, lane, warpM, warpN);

    if (t < 2) {
        float* Out = g_qkm[t][b4];
#pragma unroll
        for (int mt = 0; mt < 2; mt++)
#pragma unroll
            for (int half = 0; half < 2; half++) {
                int w = m0 + warpM * 32 + mt * 16 + gid + half * 8;
                size_t rb = (size_t)(w >> 7) * TMB + (w & 127) * TSTR;
#pragma unroll
                for (int nt = 0; nt < 8; nt++) {
                    int f = n0 + warpN * 64 + nt * 8 + 2 * tig;
                    float v0 = acc[mt][nt][half * 2 + 0];
                    float v1 = acc[mt][nt][half * 2 + 1];
                    if (do_rope) {
                        int j0 = (f >> 1) & 63;
                        float c = g_cos[w * 64 + j0], s = g_sin[w * 64 + j0];
                        float e = v0 * c - v1 * s, o = v1 * c + v0 * s;
                        v0 = e;
                        v1 = o;
                    }
                    *(float2*)&Out[rb + (size_t)(f >> 5) * TSLAB + (f & 31)] =
                        make_float2(v0, v1);
                }
            }
    } else {
        float* ts = sh;  // reuse mainloop buffers: 128 x 132 transpose stage
        __syncthreads();
#pragma unroll
        for (int mt = 0; mt < 2; mt++)
#pragma unroll
            for (int half = 0; half < 2; half++) {
                int ml = warpM * 32 + mt * 16 + gid + half * 8;
#pragma unroll
                for (int nt = 0; nt < 8; nt++) {
                    int nl = warpN * 64 + nt * 8 + 2 * tig;
                    ts[ml * 132 + nl] = acc[mt][nt][half * 2 + 0];
                    ts[ml * 132 + nl + 1] = acc[mt][nt][half * 2 + 1];
                }
            }
        __syncthreads();
        float* Out = g_vt[b4];
        const int fl = tid >> 1, hf = tid & 1;
        int f = n0 + fl;
        size_t rb = (size_t)(f >> 7) * TMB + (f & 127) * TSTR;
#pragma unroll
        for (int i = 0; i < 64; i += 4) {
            int wl = hf * 64 + i;
            float4 v = make_float4(ts[(wl + 0) * 132 + fl], ts[(wl + 1) * 132 + fl],
                                   ts[(wl + 2) * 132 + fl], ts[(wl + 3) * 132 + fl]);
            int w = m0 + wl;
            *(float4*)&Out[rb + (size_t)(w >> 5) * TSLAB + (w & 31)] = v;
        }
    }
}

// ---------------- qk: S = qk^T/32 + prev + mask; writes S, tiled exp(S), psum ------------
__global__ __launch_bounds__(256, 2) void gemm_qk_t(const float* __restrict__ prev_qk,
                                                    const float* __restrict__ mask,
                                                    float* __restrict__ qk_out) {
    const int m0 = blockIdx.x * 128;
    const int n0 = blockIdx.y * 128;
    const int bh = blockIdx.z;
    const int b4 = bh >> 3, head = bh & 7;
    GEMM_PROLOG;

    const float* A = &g_qkm[0][b4][(size_t)(m0 >> 7) * TMB + (size_t)(head * 4) * TSLAB];
    const float* B = &g_qkm[1][b4][(size_t)(n0 >> 7) * TMB + (size_t)(head * 4) * TSLAB];
    bulk_mainloop(A, B, 4, sh, mb0, acc, tid, lane, warpM, warpN);

    const float* prevb = prev_qk + ((size_t)bh << 20);
    float* outb = qk_out + ((size_t)bh << 20);
    float* ptb = g_pt + (size_t)bh * TMAT;
#pragma unroll
    for (int mt = 0; mt < 2; mt++)
#pragma unroll
        for (int half = 0; half < 2; half++) {
            int mi = m0 + warpM * 32 + mt * 16 + gid + half * 8;
            size_t rb = (size_t)(mi >> 7) * TMB + (mi & 127) * TSTR;
            float rowsum = 0.f;
#pragma unroll
            for (int nt = 0; nt < 8; nt++) {
                int n = n0 + warpN * 64 + nt * 8 + 2 * tig;
                float2 pv = *(const float2*)&prevb[(size_t)mi * 1024 + n];
                float2 mk = *(const float2*)&mask[(size_t)mi * 1024 + n];
                float2 r;
                r.x = acc[mt][nt][half * 2 + 0] * 0.03125f + pv.x + mk.x;
                r.y = acc[mt][nt][half * 2 + 1] * 0.03125f + pv.y + mk.y;
                *(float2*)&outb[(size_t)mi * 1024 + n] = r;
                float2 e = make_float2(__expf(r.x), __expf(r.y));
                *(float2*)&ptb[rb + (size_t)(n >> 5) * TSLAB + (n & 31)] = e;
                rowsum += e.x + e.y;
            }
            rowsum += __shfl_xor_sync(0xffffffffu, rowsum, 1);
            rowsum += __shfl_xor_sync(0xffffffffu, rowsum, 2);
            if (tig == 0)
                g_psum[((size_t)bh * 1024 + mi) * 16 + blockIdx.y * 2 + warpN] = rowsum;
        }
}

// ---------------- pv: A_att = (exp(S) @ V) * rinv ----------------
__global__ __launch_bounds__(256, 2) void gemm_pv_t() {
    const int m0 = blockIdx.x * 128;
    const int bh = blockIdx.y;
    const int b4 = bh >> 3, head = bh & 7;
    GEMM_PROLOG;

    const float* A = g_pt + (size_t)bh * TMAT + (size_t)(m0 >> 7) * TMB;
    const float* B = &g_vt[b4][(size_t)head * TMB];
    bulk_mainloop(A, B, 32, sh, mb0, acc, tid, lane, warpM, warpN);

    __syncthreads();
    float* srinv = sh;
    {
        int row = tid >> 1, hh = tid & 1;
        const float* ps = &g_psum[((size_t)bh * 1024 + m0 + row) * 16 + hh * 8];
        float s = 0.f;
#pragma unroll
        for (int i = 0; i < 8; i++) s += ps[i];
        s += __shfl_xor_sync(0xffffffffu, s, 1);
        if (hh == 0) srinv[row] = 1.0f / s;
    }
    __syncthreads();

    float* Ab = g_a[b4];
#pragma unroll
    for (int mt = 0; mt < 2; mt++)
#pragma unroll
        for (int half = 0; half < 2; half++) {
            int ml = warpM * 32 + mt * 16 + gid + half * 8;
            int mi = m0 + ml;
            float rv = srinv[ml];
#pragma unroll
            for (int nt = 0; nt < 8; nt++) {
                int n = warpN * 64 + nt * 8 + 2 * tig;
                float2 r = make_float2(acc[mt][nt][half * 2 + 0] * rv,
                                       acc[mt][nt][half * 2 + 1] * rv);
                *(float2*)&Ab[(size_t)mi * 1024 + head * 128 + n] = r;
            }
        }
}

// ---------------- 4x4 depthwise channel mix -> tiled g_aot ----------------
__global__ __launch_bounds__(256) void dw_kernel(const float* __restrict__ dw) {
    int idx = blockIdx.x * 256 + threadIdx.x;
    int b = idx >> 18;
    size_t off = ((size_t)(idx & 262143)) << 2;
    int w = (int)(off >> 10), h = (int)(off & 1023);
    size_t toff = tiled_off(w, h);
    float4 a[4];
#pragma unroll
    for (int c = 0; c < 4; c++) a[c] = *(const float4*)&g_a[b * 4 + c][off];
#pragma unroll
    for (int o = 0; o < 4; o++) {
        float w0 = dw[o * 4 + 0], w1 = dw[o * 4 + 1], w2 = dw[o * 4 + 2], w3 = dw[o * 4 + 3];
        float4 r;
        r.x = w0 * a[0].x + w1 * a[1].x + w2 * a[2].x + w3 * a[3].x;
        r.y = w0 * a[0].y + w1 * a[1].y + w2 * a[2].y + w3 * a[3].y;
        r.z = w0 * a[0].z + w1 * a[1].z + w2 * a[2].z + w3 * a[3].z;
        r.w = w0 * a[0].w + w1 * a[1].w + w2 * a[2].w + w3 * a[3].w;
        *(float4*)&g_aot[b * 4 + o][toff] = r;
    }
}

// ---------------- wo_pw: Out[f][w] = W * Ao^T (plain out) ----------------
__global__ __launch_bounds__(256, 2) void gemm_wo_t() {
    const int m0 = blockIdx.x * 128;  // f
    const int n0 = blockIdx.y * 128;  // w
    const int b4 = blockIdx.z;
    const int am = b4 & 3;
    GEMM_PROLOG;

    const float* A = &g_wt[3][am][(size_t)(m0 >> 7) * TMB];
    const float* B = &g_aot[b4][(size_t)(n0 >> 7) * TMB];
    bulk_mainloop(A, B, 32, sh, mb0, acc, tid, lane, warpM, warpN);

    float* Out = g_a2[b4];
#pragma unroll
    for (int mt = 0; mt < 2; mt++)
#pragma unroll
        for (int half = 0; half < 2; half++) {
            int mi = m0 + warpM * 32 + mt * 16 + gid + half * 8;
#pragma unroll
            for (int nt = 0; nt < 8; nt++) {
                int n = n0 + warpN * 64 + nt * 8 + 2 * tig;
                float2 r = make_float2(acc[mt][nt][half * 2 + 0], acc[mt][nt][half * 2 + 1]);
                *(float2*)&Out[(size_t)mi * 1024 + n] = r;
            }
        }
}

// ---------------- final conv 3x3 over concat(x[16], a2[4]) -> 16 channels ----------------
__global__ __launch_bounds__(256) void conv_out_kernel(const float* __restrict__ x,
                                                       const float* __restrict__ wo,
                                                       const float* __restrict__ bo,
                                                       float* __restrict__ out) {
    __shared__ float sx[4][18][68];
    __shared__ float sw[16 * 20 * 9];
    const int b = blockIdx.x;
    const int h0 = blockIdx.y * 16;
    const int w0 = blockIdx.z * 64;
    const int tx = threadIdx.x, ty = threadIdx.y;
    const int tid = ty * 16 + tx;

    for (int i = tid; i < 2880; i += 256) sw[i] = wo[i];

    float acc[16][4];
#pragma unroll
    for (int o = 0; o < 16; o++)
#pragma unroll
        for (int p = 0; p < 4; p++) acc[o][p] = 0.f;

    for (int cc = 0; cc < 20; cc += 4) {
        __syncthreads();
        for (int e = tid; e < 4 * 18 * 66; e += 256) {
            int ch = e / (18 * 66);
            int r = (e / 66) % 18;
            int cl = e % 66;
            int gh = h0 + r - 1, gw = w0 + cl - 1;
            int c = cc + ch;
            float v = 0.f;
            if ((unsigned)gh < 1024u && (unsigned)gw < 1024u) {
                const float* src = (c < 16) ? (x + (((size_t)(b * 16 + c)) << 20))
                                            : g_a2[b * 4 + (c - 16)];
                v = src[gh * 1024 + gw];
            }
            sx[ch][r][cl] = v;
        }
        __syncthreads();
#pragma unroll
        for (int ch = 0; ch < 4; ch++) {
#pragma unroll
            for (int dy = 0; dy < 3; dy++) {
                float xr[6];
#pragma unroll
                for (int i = 0; i < 6; i++) xr[i] = sx[ch][ty + dy][tx * 4 + i];
#pragma unroll
                for (int dx = 0; dx < 3; dx++) {
                    int widx = (cc + ch) * 9 + dy * 3 + dx;
#pragma unroll
                    for (int o = 0; o < 16; o++) {
                        float wv_ = sw[o * 180 + widx];
#pragma unroll
                        for (int p = 0; p < 4; p++) acc[o][p] += wv_ * xr[p + dx];
                    }
                }
            }
        }
    }

    int gh = h0 + ty, gw = w0 + tx * 4;
#pragma unroll
    for (int o = 0; o < 16; o++) {
        float bb = bo[o];
        float4 v = make_float4(acc[o][0] + bb, acc[o][1] + bb, acc[o][2] + bb, acc[o][3] + bb);
        *(float4*)&out[(((size_t)(b * 16 + o)) << 20) + gh * 1024 + gw] = v;
    }
}

// ---------------- launch ----------------
extern "C" void kernel_launch(void* const* d_in, const int* in_sizes, int n_in,
                              void* d_out, int out_size) {
    const float* x       = (const float*)d_in[0];
    const float* prev_qk = (const float*)d_in[1];
    const float* mask    = (const float*)d_in[2];
    const float* wq_conv = (const float*)d_in[3];
    const float* bq_conv = (const float*)d_in[4];
    const float* wq_pw   = (const float*)d_in[5];
    const float* wk_conv = (const float*)d_in[6];
    const float* bk_conv = (const float*)d_in[7];
    const float* wk_pw   = (const float*)d_in[8];
    const float* wv_conv = (const float*)d_in[9];
    const float* bv_conv = (const float*)d_in[10];
    const float* wv_pw   = (const float*)d_in[11];
    const float* wo_pw   = (const float*)d_in[12];
    const float* wo_dw   = (const float*)d_in[13];
    const float* wo_conv = (const float*)d_in[14];
    const float* bo_conv = (const float*)d_in[15];

    float* outp = (float*)d_out;                       // (2,16,1024,1024)
    float* qk_out = outp + (size_t)NB * NC * NF * NW;  // (2,4,8,1024,1024)

    const int GM_SM = 4 * TSLAB_B;  // 73728

    cudaFuncSetAttribute(gemm_pw_t, cudaFuncAttributeMaxDynamicSharedMemorySize, GM_SM);
    cudaFuncSetAttribute(gemm_qk_t, cudaFuncAttributeMaxDynamicSharedMemorySize, GM_SM);
    cudaFuncSetAttribute(gemm_pv_t, cudaFuncAttributeMaxDynamicSharedMemorySize, GM_SM);
    cudaFuncSetAttribute(gemm_wo_t, cudaFuncAttributeMaxDynamicSharedMemorySize, GM_SM);

    rope_init_kernel<<<64, 1024>>>();
    repack_kernel<<<dim3(8, 32, 4), 256>>>(wq_pw, 0);
    repack_kernel<<<dim3(8, 32, 4), 256>>>(wk_pw, 1);
    repack_kernel<<<dim3(8, 32, 4), 256>>>(wv_pw, 2);
    repack_kernel<<<dim3(8, 32, 4), 256>>>(wo_pw, 3);
    conv_qkv_kernel<<<dim3(NB, 64, 16), dim3(16, 16)>>>(x, wq_conv, bq_conv,
                                                        wk_conv, bk_conv, wv_conv, bv_conv);
    gemm_pw_t<<<dim3(8, 8, 8), 256, GM_SM>>>(0, 1);
    gemm_pw_t<<<dim3(8, 8, 8), 256, GM_SM>>>(1, 1);
    gemm_pw_t<<<dim3(8, 8, 8), 256, GM_SM>>>(2, 0);
    gemm_qk_t<<<dim3(8, 8, 64), 256, GM_SM>>>(prev_qk, mask, qk_out);
    gemm_pv_t<<<dim3(8, 64), 256, GM_SM>>>();
    dw_kernel<<<2048, 256>>>(wo_dw);
    gemm_wo_t<<<dim3(8, 8, 8), 256, GM_SM>>>();
    conv_out_kernel<<<dim3(NB, 64, 16), dim3(16, 16)>>>(x, wo_conv, bo_conv, outp);
}